// round 5
// baseline (speedup 1.0000x reference)
#include <cuda_runtime.h>
#include <cstdint>
#include <math.h>

// GPT forward: B=4, T=512, L=12, C=1024, H=16, HD=64, F=4096, V=32000
#define Bn   4
#define Tn   512
#define Ln   12
#define Cn   1024
#define Hn   16
#define HDn  64
#define Fn   4096
#define Vn   32000
#define BT   (Bn * Tn)          // 2048
#define C3   (3 * Cn)           // 3072

// ---------------- static scratch (no allocations allowed) ----------------
__device__ float g_x  [BT * Cn];
__device__ float g_xn [BT * Cn];
__device__ float g_qkv[BT * C3];
__device__ float g_y  [BT * Cn];
__device__ float g_h  [BT * Fn];
// tf32-rounded weights; wq/wk/wv packed into [C, 3C] per layer
__device__ float g_wqkvR[(size_t)Ln * Cn * C3];
__device__ float g_woR[Ln * Cn * Cn];
__device__ float g_w1R[Ln * Cn * Fn];
__device__ float g_w2R[Ln * Fn * Cn];
__device__ float g_wlmR[(size_t)Vn * Cn];

__device__ __forceinline__ uint32_t f2tf32(float f) {
    uint32_t u;
    asm("cvt.rna.tf32.f32 %0, %1;" : "=r"(u) : "f"(f));
    return u;
}
__device__ __forceinline__ float roundtf(float f) {
    return __uint_as_float(f2tf32(f));
}
__device__ __forceinline__ uint32_t smem_u32(const void* p) {
    uint32_t a;
    asm("{ .reg .u64 t; cvta.to.shared.u64 t, %1; cvt.u32.u64 %0, t; }"
        : "=r"(a) : "l"(p));
    return a;
}
__device__ __forceinline__ void cp16(void* s, const void* g) {
    asm volatile("cp.async.cg.shared.global [%0], [%1], 16;"
                 :: "r"(smem_u32(s)), "l"(g) : "memory");
}
#define CP_COMMIT() asm volatile("cp.async.commit_group;" ::: "memory")
#define CP_WAIT1()  asm volatile("cp.async.wait_group 1;" ::: "memory")
#define CP_WAIT0()  asm volatile("cp.async.wait_group 0;" ::: "memory")

// ---------------- one-shot weight rounding / packing ---------------------
#define N_QKVO (Ln * Cn * Cn)          // 12,582,912
#define N_FF   (Ln * Cn * Fn)          // 50,331,648
#define N_LM   ((size_t)Vn * Cn)       // 32,768,000

__global__ void round_weights(const float* wq, const float* wk, const float* wv,
                              const float* wo, const float* w1, const float* w2,
                              const float* wlm,
                              float* wqkvR, float* woR,
                              float* w1R, float* w2R, float* wlmR) {
    const float* in; float* out; size_t n;
    int sel = -1;
    switch (blockIdx.y) {
        case 0: in = wq;  out = wqkvR; n = N_QKVO; sel = 0; break;
        case 1: in = wk;  out = wqkvR; n = N_QKVO; sel = 1; break;
        case 2: in = wv;  out = wqkvR; n = N_QKVO; sel = 2; break;
        case 3: in = wo;  out = woR;  n = N_QKVO; break;
        case 4: in = w1;  out = w1R;  n = N_FF;   break;
        case 5: in = w2;  out = w2R;  n = N_FF;   break;
        default: in = wlm; out = wlmR; n = N_LM;  break;
    }
    size_t i = ((size_t)blockIdx.x * 256 + threadIdx.x) * 4;
    if (i >= n) return;
    float4 v = *(const float4*)(in + i);
    v.x = roundtf(v.x); v.y = roundtf(v.y);
    v.z = roundtf(v.z); v.w = roundtf(v.w);
    size_t oi = i;
    if (sel >= 0) {
        size_t l = i / (Cn * Cn);
        size_t rem = i - l * Cn * Cn;
        size_t kk = rem / Cn, nn = rem % Cn;
        oi = (l * Cn + kk) * C3 + (size_t)sel * Cn + nn;
    }
    *(float4*)(out + oi) = v;
}

// ---------------- embedding (x stays fp32: residual stream) --------------
__global__ void embed_kernel(const int* __restrict__ idx,
                             const float* __restrict__ tok,
                             const float* __restrict__ pos,
                             float* __restrict__ x) {
    int row = blockIdx.x;
    int t = row & (Tn - 1);
    int token = idx[row];
    const float* tp = tok + (size_t)token * Cn;
    const float* pp = pos + (size_t)t * Cn;
    float* xp = x + (size_t)row * Cn;
    for (int c = threadIdx.x; c < Cn; c += 256)
        xp[c] = tp[c] + pp[c];
}

// ---------------- layernorm (output tf32-rounded: feeds GEMM A) ----------
__global__ void ln_kernel(const float* __restrict__ in,
                          const float* __restrict__ g,
                          const float* __restrict__ b,
                          float* __restrict__ out) {
    int row = blockIdx.x;
    int tid = threadIdx.x;
    const float* p = in + (size_t)row * Cn;
    float s = 0.f, sq = 0.f;
    for (int c = tid; c < Cn; c += 256) { float v = p[c]; s += v; sq += v * v; }
    __shared__ float rs[256], rq[256];
    rs[tid] = s; rq[tid] = sq; __syncthreads();
    for (int o = 128; o > 0; o >>= 1) {
        if (tid < o) { rs[tid] += rs[tid + o]; rq[tid] += rq[tid + o]; }
        __syncthreads();
    }
    float mean = rs[0] * (1.f / Cn);
    float var  = rq[0] * (1.f / Cn) - mean * mean;
    float inv  = rsqrtf(var + 1e-5f);
    float* op = out + (size_t)row * Cn;
    for (int c = tid; c < Cn; c += 256)
        op[c] = roundtf((p[c] - mean) * inv * g[c] + b[c]);
}

// ---------------- tf32 mma GEMM: C[M,N] = A[M,K] @ B[K,N] ----------------
// CTA tile MTILE x 128, BK=32, 8 warps, cp.async double buffer.
// MTILE=128: warps 2(m)x4(n), warp tile 64x32 (MI=4)
// MTILE=64 : warps 2(m)x4(n), warp tile 32x32 (MI=2)
#define APAD 36
#define BPAD 136
#define BSZ (32 * BPAD)

template<int MTILE, bool RELU, bool ROUND>
__global__ __launch_bounds__(256, 2)
void gemm_mma(const float* __restrict__ A, const float* __restrict__ B,
              const float* __restrict__ bias, const float* __restrict__ res,
              float* __restrict__ C, int N, int K) {
    constexpr int MI = MTILE / 32;               // 4 or 2
    constexpr int ASZ = MTILE * APAD;
    constexpr int STAGEF = ASZ + BSZ;
    constexpr int NA = MTILE / 32;               // A float4 loads per thread
    extern __shared__ float sm[];
    const int tid = threadIdx.x;
    const int lane = tid & 31, wid = tid >> 5;
    const int warp_m = (wid & 1) * (MI * 16);
    const int warp_n = (wid >> 1) << 5;
    const int m0 = blockIdx.y * MTILE;
    const int n0 = blockIdx.x * 128;

    const float* aptr[NA]; const float* bptr[4];
    int saoff[NA], sboff[4];
    #pragma unroll
    for (int j = 0; j < NA; j++) {
        int ia = j * 256 + tid;
        int ar = ia >> 3, ac = (ia & 7) << 2;
        aptr[j] = A + (size_t)(m0 + ar) * K + ac;
        saoff[j] = ar * APAD + ac;
    }
    #pragma unroll
    for (int j = 0; j < 4; j++) {
        int ib = j * 256 + tid;
        int bk = ib >> 5, bc = (ib & 31) << 2;
        bptr[j] = B + (size_t)bk * N + n0 + bc;
        sboff[j] = bk * BPAD + bc;
    }

    const int nk = K >> 5;
    {
        float* As = sm; float* Bs = sm + ASZ;
        #pragma unroll
        for (int j = 0; j < NA; j++) cp16(As + saoff[j], aptr[j]);
        #pragma unroll
        for (int j = 0; j < 4; j++) cp16(Bs + sboff[j], bptr[j]);
        CP_COMMIT();
    }

    float acc[MI][4][4];
    #pragma unroll
    for (int mi = 0; mi < MI; mi++)
        #pragma unroll
        for (int ni = 0; ni < 4; ni++)
            #pragma unroll
            for (int r = 0; r < 4; r++) acc[mi][ni][r] = 0.f;

    for (int it = 0; it < nk; ++it) {
        if (it + 1 < nk) {
            const int kk = (it + 1) << 5;
            float* As = sm + ((it + 1) & 1) * STAGEF;
            float* Bs = As + ASZ;
            #pragma unroll
            for (int j = 0; j < NA; j++) cp16(As + saoff[j], aptr[j] + kk);
            #pragma unroll
            for (int j = 0; j < 4; j++) cp16(Bs + sboff[j], bptr[j] + (size_t)kk * N);
            CP_COMMIT();
            CP_WAIT1();
        } else {
            CP_WAIT0();
        }
        __syncthreads();

        const float* Ac = sm + (it & 1) * STAGEF;
        const float* Bc = Ac + ASZ;
        #pragma unroll
        for (int ks = 0; ks < 4; ks++) {
            const int kb = ks * 8;
            uint32_t af[MI][4], bf[4][2];
            #pragma unroll
            for (int mi = 0; mi < MI; mi++) {
                int rl = warp_m + mi * 16 + (lane >> 2);
                int kc = kb + (lane & 3);
                af[mi][0] = __float_as_uint(Ac[rl * APAD + kc]);
                af[mi][1] = __float_as_uint(Ac[(rl + 8) * APAD + kc]);
                af[mi][2] = __float_as_uint(Ac[rl * APAD + kc + 4]);
                af[mi][3] = __float_as_uint(Ac[(rl + 8) * APAD + kc + 4]);
            }
            #pragma unroll
            for (int ni = 0; ni < 4; ni++) {
                int nn = warp_n + ni * 8 + (lane >> 2);
                int kc = kb + (lane & 3);
                bf[ni][0] = __float_as_uint(Bc[kc * BPAD + nn]);
                bf[ni][1] = __float_as_uint(Bc[(kc + 4) * BPAD + nn]);
            }
            #pragma unroll
            for (int mi = 0; mi < MI; mi++)
                #pragma unroll
                for (int ni = 0; ni < 4; ni++) {
                    asm volatile(
                        "mma.sync.aligned.m16n8k8.row.col.f32.tf32.tf32.f32 "
                        "{%0,%1,%2,%3}, {%4,%5,%6,%7}, {%8,%9}, {%0,%1,%2,%3};"
                        : "+f"(acc[mi][ni][0]), "+f"(acc[mi][ni][1]),
                          "+f"(acc[mi][ni][2]), "+f"(acc[mi][ni][3])
                        : "r"(af[mi][0]), "r"(af[mi][1]), "r"(af[mi][2]), "r"(af[mi][3]),
                          "r"(bf[ni][0]), "r"(bf[ni][1]));
                }
        }
        __syncthreads();
    }

    #pragma unroll
    for (int mi = 0; mi < MI; mi++) {
        int row = m0 + warp_m + mi * 16 + (lane >> 2);
        #pragma unroll
        for (int ni = 0; ni < 4; ni++) {
            int col = n0 + warp_n + ni * 8 + ((lane & 3) << 1);
            float v0 = acc[mi][ni][0], v1 = acc[mi][ni][1];
            float v2 = acc[mi][ni][2], v3 = acc[mi][ni][3];
            if (bias) {
                float b0 = bias[col], b1 = bias[col + 1];
                v0 += b0; v1 += b1; v2 += b0; v3 += b1;
            }
            if (RELU) {
                v0 = fmaxf(v0, 0.f); v1 = fmaxf(v1, 0.f);
                v2 = fmaxf(v2, 0.f); v3 = fmaxf(v3, 0.f);
            }
            if (res) {
                const float2 r0 = *(const float2*)(res + (size_t)row * N + col);
                const float2 r1 = *(const float2*)(res + (size_t)(row + 8) * N + col);
                v0 += r0.x; v1 += r0.y; v2 += r1.x; v3 += r1.y;
            }
            if (ROUND) {
                v0 = roundtf(v0); v1 = roundtf(v1);
                v2 = roundtf(v2); v3 = roundtf(v3);
            }
            *(float2*)(C + (size_t)row * N + col) = make_float2(v0, v1);
            *(float2*)(C + (size_t)(row + 8) * N + col) = make_float2(v2, v3);
        }
    }
}

#define SMEM_128 ((128 * APAD + BSZ) * 2 * 4)
#define SMEM_64  ((64 * APAD + BSZ) * 2 * 4)

// ---------------- flash attention on interleaved qkv ----------------------
__global__ __launch_bounds__(64)
void attn_flash(const float* __restrict__ qkv, float* __restrict__ y) {
    const int tt = blockIdx.x, h = blockIdx.y, b = blockIdx.z;
    const int tid = threadIdx.x;
    __shared__ float ks[64 * 64];
    __shared__ float vs[64 * 64];
    const size_t base = (size_t)b * Tn * C3 + (size_t)h * HDn;
    const int t0 = tt * 64;

    for (int i = tid; i < 4096; i += 64)
        ks[i] = qkv[base + (size_t)(t0 + (i >> 6)) * C3 + (i & 63)];
    __syncthreads();
    float qr[64];
    #pragma unroll
    for (int d = 0; d < 64; d++) qr[d] = ks[tid * 64 + d] * 0.125f;
    __syncthreads();

    float m = -1e30f, l = 0.f;
    float acc[64];
    #pragma unroll
    for (int d = 0; d < 64; d++) acc[d] = 0.f;

    for (int st = 0; st <= tt; ++st) {
        const int s0 = st * 64;
        for (int i = tid; i < 4096; i += 64) {
            size_t gi = base + (size_t)(s0 + (i >> 6)) * C3 + (i & 63);
            ks[i] = qkv[gi + Cn];          // K
            vs[i] = qkv[gi + 2 * Cn];      // V
        }
        __syncthreads();
        const int smax = (st == tt) ? tid : 63;

        float tm = m;
        for (int s = 0; s <= smax; ++s) {
            const float4* kp = (const float4*)(ks + s * 64);
            float d = 0.f;
            #pragma unroll
            for (int j = 0; j < 16; j++) {
                float4 kv = kp[j];
                d += qr[4*j] * kv.x + qr[4*j+1] * kv.y
                   + qr[4*j+2] * kv.z + qr[4*j+3] * kv.w;
            }
            tm = fmaxf(tm, d);
        }
        float scale = __expf(m - tm);
        l *= scale;
        #pragma unroll
        for (int d = 0; d < 64; d++) acc[d] *= scale;
        m = tm;

        for (int s = 0; s <= smax; ++s) {
            const float4* kp = (const float4*)(ks + s * 64);
            float d = 0.f;
            #pragma unroll
            for (int j = 0; j < 16; j++) {
                float4 kv = kp[j];
                d += qr[4*j] * kv.x + qr[4*j+1] * kv.y
                   + qr[4*j+2] * kv.z + qr[4*j+3] * kv.w;
            }
            float p = __expf(d - m);
            l += p;
            const float4* vp = (const float4*)(vs + s * 64);
            #pragma unroll
            for (int j = 0; j < 16; j++) {
                float4 vv = vp[j];
                acc[4*j]   += p * vv.x; acc[4*j+1] += p * vv.y;
                acc[4*j+2] += p * vv.z; acc[4*j+3] += p * vv.w;
            }
        }
        __syncthreads();
    }

    const float inv = 1.f / l;
    #pragma unroll
    for (int d = 0; d < 64; d++) ks[tid * 64 + d] = acc[d] * inv;
    __syncthreads();
    const size_t ybase = (size_t)b * Tn * Cn + (size_t)h * HDn;
    for (int i = tid; i < 4096; i += 64)
        y[ybase + (size_t)(t0 + (i >> 6)) * Cn + (i & 63)] = roundtf(ks[i]);
}

// ---------------- launch ----------------
extern "C" void kernel_launch(void* const* d_in, const int* in_sizes, int n_in,
                              void* d_out, int out_size) {
    const int*   idx   = (const int*)  d_in[0];
    const float* tok   = (const float*)d_in[1];
    const float* pos   = (const float*)d_in[2];
    const float* wq    = (const float*)d_in[3];
    const float* wk    = (const float*)d_in[4];
    const float* wv    = (const float*)d_in[5];
    const float* wo    = (const float*)d_in[6];
    const float* bo    = (const float*)d_in[7];
    const float* ln1g  = (const float*)d_in[8];
    const float* ln1b  = (const float*)d_in[9];
    const float* ln2g  = (const float*)d_in[10];
    const float* ln2b  = (const float*)d_in[11];
    const float* w1    = (const float*)d_in[12];
    const float* b1    = (const float*)d_in[13];
    const float* w2    = (const float*)d_in[14];
    const float* b2    = (const float*)d_in[15];
    const float* lnfg  = (const float*)d_in[16];
    const float* lnfb  = (const float*)d_in[17];
    const float* wlm   = (const float*)d_in[18];
    float* out = (float*)d_out;

    float *x, *xn, *qkv, *y, *h;
    float *wqkvR, *woR, *w1R, *w2R, *wlmR;
    cudaGetSymbolAddress((void**)&x,   g_x);
    cudaGetSymbolAddress((void**)&xn,  g_xn);
    cudaGetSymbolAddress((void**)&qkv, g_qkv);
    cudaGetSymbolAddress((void**)&y,   g_y);
    cudaGetSymbolAddress((void**)&h,   g_h);
    cudaGetSymbolAddress((void**)&wqkvR, g_wqkvR);
    cudaGetSymbolAddress((void**)&woR, g_woR);
    cudaGetSymbolAddress((void**)&w1R, g_w1R);
    cudaGetSymbolAddress((void**)&w2R, g_w2R);
    cudaGetSymbolAddress((void**)&wlmR, g_wlmR);

    cudaFuncSetAttribute(gemm_mma<128, false, false>,
                         cudaFuncAttributeMaxDynamicSharedMemorySize, SMEM_128);
    cudaFuncSetAttribute(gemm_mma<128, true, true>,
                         cudaFuncAttributeMaxDynamicSharedMemorySize, SMEM_128);
    cudaFuncSetAttribute(gemm_mma<64, false, false>,
                         cudaFuncAttributeMaxDynamicSharedMemorySize, SMEM_64);

    // launch 0: round+pack all weights
    round_weights<<<dim3(N_FF / 4 / 256, 7), 256>>>(
        wq, wk, wv, wo, w1, w2, wlm, wqkvR, woR, w1R, w2R, wlmR);
    // launch 1
    embed_kernel<<<BT, 256>>>(idx, tok, pos, x);

    const dim3 gQKV(C3 / 128, BT / 128);   // 24 x 16 = 384
    const dim3 gCC64(Cn / 128, BT / 64);   // 8 x 32 = 256
    const dim3 gCF(Fn / 128, BT / 128);    // 32 x 16 = 512
    const dim3 gCV(Vn / 128, BT / 128);    // 250 x 16
    const dim3 gAttn(Tn / 64, Hn, Bn);     // 8 x 16 x 4

    for (int l = 0; l < Ln; l++) {
        const float* wqkvl = wqkvR + (size_t)l * Cn * C3;
        const float* woRl = woR + (size_t)l * Cn * Cn;
        const float* bol  = bo + (size_t)l * Cn;
        const float* w1Rl = w1R + (size_t)l * Cn * Fn;
        const float* b1l  = b1 + (size_t)l * Fn;
        const float* w2Rl = w2R + (size_t)l * Fn * Cn;
        const float* b2l  = b2 + (size_t)l * Cn;

        ln_kernel<<<BT, 256>>>(x, ln1g + l * Cn, ln1b + l * Cn, xn);
        gemm_mma<128, false, false><<<gQKV, 256, SMEM_128>>>(xn, wqkvl, nullptr, nullptr, qkv, C3, Cn);
        attn_flash<<<gAttn, 64>>>(qkv, y);
        gemm_mma<64, false, false><<<gCC64, 256, SMEM_64>>>(y, woRl, bol, x, x, Cn, Cn);

        ln_kernel<<<BT, 256>>>(x, ln2g + l * Cn, ln2b + l * Cn, xn);
        gemm_mma<128, true, true><<<gCF, 256, SMEM_128>>>(xn, w1Rl, b1l, nullptr, h, Fn, Cn);
        gemm_mma<64, false, false><<<gCC64, 256, SMEM_64>>>(h, w2Rl, b2l, x, x, Cn, Fn);
    }

    ln_kernel<<<BT, 256>>>(x, lnfg, lnfb, xn);
    gemm_mma<128, false, false><<<gCV, 256, SMEM_128>>>(xn, wlmR, nullptr, nullptr, out, Vn, Cn);
}

// round 6
// speedup vs baseline: 1.1471x; 1.1471x over previous
#include <cuda_runtime.h>
#include <cstdint>
#include <math.h>

// GPT forward: B=4, T=512, L=12, C=1024, H=16, HD=64, F=4096, V=32000
#define Bn   4
#define Tn   512
#define Ln   12
#define Cn   1024
#define Hn   16
#define HDn  64
#define Fn   4096
#define Vn   32000
#define BT   (Bn * Tn)          // 2048
#define C3   (3 * Cn)           // 3072

// ---------------- static scratch (no allocations allowed) ----------------
__device__ float g_x  [BT * Cn];
__device__ float g_xn [BT * Cn];
__device__ float g_qkv[BT * C3];
__device__ float g_y  [BT * Cn];
__device__ float g_h  [BT * Fn];
// tf32-rounded weights; wq/wk/wv packed into [C, 3C] per layer
__device__ float g_wqkvR[(size_t)Ln * Cn * C3];
__device__ float g_woR[Ln * Cn * Cn];
__device__ float g_w1R[Ln * Cn * Fn];
__device__ float g_w2R[Ln * Fn * Cn];
__device__ float g_wlmR[(size_t)Vn * Cn];

__device__ __forceinline__ uint32_t f2tf32(float f) {
    uint32_t u;
    asm("cvt.rna.tf32.f32 %0, %1;" : "=r"(u) : "f"(f));
    return u;
}
__device__ __forceinline__ float roundtf(float f) {
    return __uint_as_float(f2tf32(f));
}
__device__ __forceinline__ uint32_t smem_u32(const void* p) {
    uint32_t a;
    asm("{ .reg .u64 t; cvta.to.shared.u64 t, %1; cvt.u32.u64 %0, t; }"
        : "=r"(a) : "l"(p));
    return a;
}
__device__ __forceinline__ void cp16(void* s, const void* g) {
    asm volatile("cp.async.cg.shared.global [%0], [%1], 16;"
                 :: "r"(smem_u32(s)), "l"(g) : "memory");
}
#define CP_COMMIT() asm volatile("cp.async.commit_group;" ::: "memory")
#define CP_WAIT1()  asm volatile("cp.async.wait_group 1;" ::: "memory")

// ---------------- one-shot weight rounding / packing ---------------------
#define N_QKVO (Ln * Cn * Cn)          // 12,582,912
#define N_FF   (Ln * Cn * Fn)          // 50,331,648
#define N_LM   ((size_t)Vn * Cn)       // 32,768,000

__global__ void round_weights(const float* wq, const float* wk, const float* wv,
                              const float* wo, const float* w1, const float* w2,
                              const float* wlm,
                              float* wqkvR, float* woR,
                              float* w1R, float* w2R, float* wlmR) {
    const float* in; float* out; size_t n;
    int sel = -1;
    switch (blockIdx.y) {
        case 0: in = wq;  out = wqkvR; n = N_QKVO; sel = 0; break;
        case 1: in = wk;  out = wqkvR; n = N_QKVO; sel = 1; break;
        case 2: in = wv;  out = wqkvR; n = N_QKVO; sel = 2; break;
        case 3: in = wo;  out = woR;  n = N_QKVO; break;
        case 4: in = w1;  out = w1R;  n = N_FF;   break;
        case 5: in = w2;  out = w2R;  n = N_FF;   break;
        default: in = wlm; out = wlmR; n = N_LM;  break;
    }
    size_t i = ((size_t)blockIdx.x * 256 + threadIdx.x) * 4;
    if (i >= n) return;
    float4 v = *(const float4*)(in + i);
    v.x = roundtf(v.x); v.y = roundtf(v.y);
    v.z = roundtf(v.z); v.w = roundtf(v.w);
    size_t oi = i;
    if (sel >= 0) {
        size_t l = i / (Cn * Cn);
        size_t rem = i - l * Cn * Cn;
        size_t kk = rem / Cn, nn = rem % Cn;
        oi = (l * Cn + kk) * C3 + (size_t)sel * Cn + nn;
    }
    *(float4*)(out + oi) = v;
}

// ---------------- embedding (x stays fp32: residual stream) --------------
__global__ void embed_kernel(const int* __restrict__ idx,
                             const float* __restrict__ tok,
                             const float* __restrict__ pos,
                             float* __restrict__ x) {
    int row = blockIdx.x;
    int t = row & (Tn - 1);
    int token = idx[row];
    const float* tp = tok + (size_t)token * Cn;
    const float* pp = pos + (size_t)t * Cn;
    float* xp = x + (size_t)row * Cn;
    for (int c = threadIdx.x; c < Cn; c += 256)
        xp[c] = tp[c] + pp[c];
}

// ---------------- layernorm (output tf32-rounded: feeds GEMM A) ----------
__global__ void ln_kernel(const float* __restrict__ in,
                          const float* __restrict__ g,
                          const float* __restrict__ b,
                          float* __restrict__ out) {
    int row = blockIdx.x;
    int tid = threadIdx.x;
    const float* p = in + (size_t)row * Cn;
    float s = 0.f, sq = 0.f;
    for (int c = tid; c < Cn; c += 256) { float v = p[c]; s += v; sq += v * v; }
    __shared__ float rs[256], rq[256];
    rs[tid] = s; rq[tid] = sq; __syncthreads();
    for (int o = 128; o > 0; o >>= 1) {
        if (tid < o) { rs[tid] += rs[tid + o]; rq[tid] += rq[tid + o]; }
        __syncthreads();
    }
    float mean = rs[0] * (1.f / Cn);
    float var  = rq[0] * (1.f / Cn) - mean * mean;
    float inv  = rsqrtf(var + 1e-5f);
    float* op = out + (size_t)row * Cn;
    for (int c = tid; c < Cn; c += 256)
        op[c] = roundtf((p[c] - mean) * inv * g[c] + b[c]);
}

// ---------------- tf32 mma GEMM: C[M,N] = A[M,K] @ B[K,N] ----------------
// CTA 128x128, BK=32, 8 warps (warp tile 64x32), 3-stage cp.async pipeline,
// ONE __syncthreads per K-chunk, 2 CTAs/SM.
#define APAD 36
#define BPAD 136
#define ASZ (128 * APAD)               // 4608 floats
#define BSZ (32 * BPAD)                // 4352 floats
#define STAGEF (ASZ + BSZ)             // 8960 floats
#define GEMM_SMEM (3 * STAGEF * 4)     // 107520 bytes

template<bool RELU, bool ROUND>
__global__ __launch_bounds__(256, 2)
void gemm_mma(const float* __restrict__ A, const float* __restrict__ B,
              const float* __restrict__ bias, const float* __restrict__ res,
              float* __restrict__ C, int N, int K) {
    extern __shared__ float sm[];
    const int tid = threadIdx.x;
    const int lane = tid & 31, wid = tid >> 5;
    const int warp_m = (wid & 1) << 6;     // 0 or 64
    const int warp_n = (wid >> 1) << 5;    // 0,32,64,96
    const int m0 = blockIdx.y * 128;
    const int n0 = blockIdx.x * 128;

    const float* aptr[4]; const float* bptr[4];
    int saoff[4], sboff[4];
    #pragma unroll
    for (int j = 0; j < 4; j++) {
        int ia = j * 256 + tid;
        int ar = ia >> 3, ac = (ia & 7) << 2;       // row 0..127, k 0,4..28
        aptr[j] = A + (size_t)(m0 + ar) * K + ac;
        saoff[j] = ar * APAD + ac;
        int bk = ia >> 5, bc = (ia & 31) << 2;      // k 0..31, n 0,4..124
        bptr[j] = B + (size_t)bk * N + n0 + bc;
        sboff[j] = bk * BPAD + bc;
    }

    const int nk = K >> 5;                 // always >= 32 here

    // prologue: stages 0 and 1
    #pragma unroll
    for (int s = 0; s < 2; s++) {
        float* As = sm + s * STAGEF;
        float* Bs = As + ASZ;
        const int kk = s << 5;
        #pragma unroll
        for (int j = 0; j < 4; j++) {
            cp16(As + saoff[j], aptr[j] + kk);
            cp16(Bs + sboff[j], bptr[j] + (size_t)kk * N);
        }
        CP_COMMIT();
    }

    float acc[4][4][4];
    #pragma unroll
    for (int mi = 0; mi < 4; mi++)
        #pragma unroll
        for (int ni = 0; ni < 4; ni++)
            #pragma unroll
            for (int r = 0; r < 4; r++) acc[mi][ni][r] = 0.f;

    int rstage = 0, wstage = 2;
    for (int it = 0; it < nk; ++it) {
        CP_WAIT1();            // group for stage `it` complete (own copies)
        __syncthreads();       // make ALL threads' copies of stage `it` visible

        const float* Ac = sm + rstage * STAGEF;
        const float* Bc = Ac + ASZ;
        #pragma unroll
        for (int ks = 0; ks < 4; ks++) {
            const int kb = ks * 8;
            uint32_t af[4][4], bf[4][2];
            #pragma unroll
            for (int mi = 0; mi < 4; mi++) {
                int rl = warp_m + mi * 16 + (lane >> 2);
                int kc = kb + (lane & 3);
                af[mi][0] = __float_as_uint(Ac[rl * APAD + kc]);
                af[mi][1] = __float_as_uint(Ac[(rl + 8) * APAD + kc]);
                af[mi][2] = __float_as_uint(Ac[rl * APAD + kc + 4]);
                af[mi][3] = __float_as_uint(Ac[(rl + 8) * APAD + kc + 4]);
            }
            #pragma unroll
            for (int ni = 0; ni < 4; ni++) {
                int nn = warp_n + ni * 8 + (lane >> 2);
                int kc = kb + (lane & 3);
                bf[ni][0] = __float_as_uint(Bc[kc * BPAD + nn]);
                bf[ni][1] = __float_as_uint(Bc[(kc + 4) * BPAD + nn]);
            }
            #pragma unroll
            for (int mi = 0; mi < 4; mi++)
                #pragma unroll
                for (int ni = 0; ni < 4; ni++) {
                    asm volatile(
                        "mma.sync.aligned.m16n8k8.row.col.f32.tf32.tf32.f32 "
                        "{%0,%1,%2,%3}, {%4,%5,%6,%7}, {%8,%9}, {%0,%1,%2,%3};"
                        : "+f"(acc[mi][ni][0]), "+f"(acc[mi][ni][1]),
                          "+f"(acc[mi][ni][2]), "+f"(acc[mi][ni][3])
                        : "r"(af[mi][0]), "r"(af[mi][1]), "r"(af[mi][2]), "r"(af[mi][3]),
                          "r"(bf[ni][0]), "r"(bf[ni][1]));
                }
        }

        // prefetch stage it+2 (its last readers passed this iteration's sync)
        if (it + 2 < nk) {
            const int kk = (it + 2) << 5;
            float* As = sm + wstage * STAGEF;
            float* Bs = As + ASZ;
            #pragma unroll
            for (int j = 0; j < 4; j++) {
                cp16(As + saoff[j], aptr[j] + kk);
                cp16(Bs + sboff[j], bptr[j] + (size_t)kk * N);
            }
        }
        CP_COMMIT();           // commit (possibly empty) to keep counts aligned

        rstage = (rstage == 2) ? 0 : rstage + 1;
        wstage = (wstage == 2) ? 0 : wstage + 1;
    }

    // epilogue
    #pragma unroll
    for (int mi = 0; mi < 4; mi++) {
        int row = m0 + warp_m + mi * 16 + (lane >> 2);
        #pragma unroll
        for (int ni = 0; ni < 4; ni++) {
            int col = n0 + warp_n + ni * 8 + ((lane & 3) << 1);
            float v0 = acc[mi][ni][0], v1 = acc[mi][ni][1];
            float v2 = acc[mi][ni][2], v3 = acc[mi][ni][3];
            if (bias) {
                float b0 = bias[col], b1 = bias[col + 1];
                v0 += b0; v1 += b1; v2 += b0; v3 += b1;
            }
            if (RELU) {
                v0 = fmaxf(v0, 0.f); v1 = fmaxf(v1, 0.f);
                v2 = fmaxf(v2, 0.f); v3 = fmaxf(v3, 0.f);
            }
            if (res) {
                const float2 r0 = *(const float2*)(res + (size_t)row * N + col);
                const float2 r1 = *(const float2*)(res + (size_t)(row + 8) * N + col);
                v0 += r0.x; v1 += r0.y; v2 += r1.x; v3 += r1.y;
            }
            if (ROUND) {
                v0 = roundtf(v0); v1 = roundtf(v1);
                v2 = roundtf(v2); v3 = roundtf(v3);
            }
            *(float2*)(C + (size_t)row * N + col) = make_float2(v0, v1);
            *(float2*)(C + (size_t)(row + 8) * N + col) = make_float2(v2, v3);
        }
    }
}

// ---------------- flash attention, single QK pass, strip-mined softmax ---
__global__ __launch_bounds__(64)
void attn_flash(const float* __restrict__ qkv, float* __restrict__ y) {
    const int tt = blockIdx.x, h = blockIdx.y, b = blockIdx.z;
    const int tid = threadIdx.x;
    __shared__ __align__(16) float ks[64 * 64];
    __shared__ __align__(16) float vs[64 * 64];
    const size_t base = (size_t)b * Tn * C3 + (size_t)h * HDn;
    const int t0 = tt * 64;

    for (int i = tid; i < 4096; i += 64)
        ks[i] = qkv[base + (size_t)(t0 + (i >> 6)) * C3 + (i & 63)];
    __syncthreads();
    float qr[64];
    #pragma unroll
    for (int d = 0; d < 64; d++) qr[d] = ks[tid * 64 + d] * 0.125f;
    __syncthreads();

    float m = -1e30f, l = 0.f;
    float acc[64];
    #pragma unroll
    for (int d = 0; d < 64; d++) acc[d] = 0.f;

    for (int st = 0; st <= tt; ++st) {
        const int s0 = st * 64;
        for (int i = tid; i < 4096; i += 64) {
            size_t gi = base + (size_t)(s0 + (i >> 6)) * C3 + (i & 63);
            ks[i] = qkv[gi + Cn];          // K
            vs[i] = qkv[gi + 2 * Cn];      // V
        }
        __syncthreads();
        const int smax = (st == tt) ? tid : 63;

        for (int ss = 0; ss <= smax; ss += 16) {
            float dd[16];
            float tm = -1e30f;
            #pragma unroll
            for (int i = 0; i < 16; i++) {
                const int s = ss + i;
                const float4* kp = (const float4*)(ks + s * 64);
                float d = 0.f;
                #pragma unroll
                for (int j = 0; j < 16; j++) {
                    float4 kv = kp[j];
                    d += qr[4*j] * kv.x + qr[4*j+1] * kv.y
                       + qr[4*j+2] * kv.z + qr[4*j+3] * kv.w;
                }
                d = (s <= smax) ? d : -1e30f;
                dd[i] = d;
                tm = fmaxf(tm, d);
            }
            if (tm > m) {
                float scl = __expf(m - tm);
                l *= scl;
                #pragma unroll
                for (int d = 0; d < 64; d++) acc[d] *= scl;
                m = tm;
            }
            #pragma unroll
            for (int i = 0; i < 16; i++) {
                const int s = ss + i;
                float p = (s <= smax) ? __expf(dd[i] - m) : 0.f;
                l += p;
                const float4* vp = (const float4*)(vs + s * 64);
                #pragma unroll
                for (int j = 0; j < 16; j++) {
                    float4 vv = vp[j];
                    acc[4*j]   += p * vv.x; acc[4*j+1] += p * vv.y;
                    acc[4*j+2] += p * vv.z; acc[4*j+3] += p * vv.w;
                }
            }
        }
        __syncthreads();
    }

    const float inv = 1.f / l;
    #pragma unroll
    for (int d = 0; d < 64; d++) ks[tid * 64 + d] = acc[d] * inv;
    __syncthreads();
    const size_t ybase = (size_t)b * Tn * Cn + (size_t)h * HDn;
    for (int i = tid; i < 4096; i += 64)
        y[ybase + (size_t)(t0 + (i >> 6)) * Cn + (i & 63)] = roundtf(ks[i]);
}

// ---------------- launch ----------------
extern "C" void kernel_launch(void* const* d_in, const int* in_sizes, int n_in,
                              void* d_out, int out_size) {
    const int*   idx   = (const int*)  d_in[0];
    const float* tok   = (const float*)d_in[1];
    const float* pos   = (const float*)d_in[2];
    const float* wq    = (const float*)d_in[3];
    const float* wk    = (const float*)d_in[4];
    const float* wv    = (const float*)d_in[5];
    const float* wo    = (const float*)d_in[6];
    const float* bo    = (const float*)d_in[7];
    const float* ln1g  = (const float*)d_in[8];
    const float* ln1b  = (const float*)d_in[9];
    const float* ln2g  = (const float*)d_in[10];
    const float* ln2b  = (const float*)d_in[11];
    const float* w1    = (const float*)d_in[12];
    const float* b1    = (const float*)d_in[13];
    const float* w2    = (const float*)d_in[14];
    const float* b2    = (const float*)d_in[15];
    const float* lnfg  = (const float*)d_in[16];
    const float* lnfb  = (const float*)d_in[17];
    const float* wlm   = (const float*)d_in[18];
    float* out = (float*)d_out;

    float *x, *xn, *qkv, *y, *h;
    float *wqkvR, *woR, *w1R, *w2R, *wlmR;
    cudaGetSymbolAddress((void**)&x,   g_x);
    cudaGetSymbolAddress((void**)&xn,  g_xn);
    cudaGetSymbolAddress((void**)&qkv, g_qkv);
    cudaGetSymbolAddress((void**)&y,   g_y);
    cudaGetSymbolAddress((void**)&h,   g_h);
    cudaGetSymbolAddress((void**)&wqkvR, g_wqkvR);
    cudaGetSymbolAddress((void**)&woR, g_woR);
    cudaGetSymbolAddress((void**)&w1R, g_w1R);
    cudaGetSymbolAddress((void**)&w2R, g_w2R);
    cudaGetSymbolAddress((void**)&wlmR, g_wlmR);

    cudaFuncSetAttribute(gemm_mma<false, false>,
                         cudaFuncAttributeMaxDynamicSharedMemorySize, GEMM_SMEM);
    cudaFuncSetAttribute(gemm_mma<true, true>,
                         cudaFuncAttributeMaxDynamicSharedMemorySize, GEMM_SMEM);

    // launch 0: round+pack all weights
    round_weights<<<dim3(N_FF / 4 / 256, 7), 256>>>(
        wq, wk, wv, wo, w1, w2, wlm, wqkvR, woR, w1R, w2R, wlmR);
    // launch 1
    embed_kernel<<<BT, 256>>>(idx, tok, pos, x);

    const dim3 gQKV(C3 / 128, BT / 128);   // 24 x 16 = 384
    const dim3 gCC(Cn / 128, BT / 128);    // 8 x 16 = 128
    const dim3 gCF(Fn / 128, BT / 128);    // 32 x 16 = 512
    const dim3 gCV(Vn / 128, BT / 128);    // 250 x 16
    const dim3 gAttn(Tn / 64, Hn, Bn);     // 8 x 16 x 4

    for (int l = 0; l < Ln; l++) {
        const float* wqkvl = wqkvR + (size_t)l * Cn * C3;
        const float* woRl = woR + (size_t)l * Cn * Cn;
        const float* bol  = bo + (size_t)l * Cn;
        const float* w1Rl = w1R + (size_t)l * Cn * Fn;
        const float* b1l  = b1 + (size_t)l * Fn;
        const float* w2Rl = w2R + (size_t)l * Fn * Cn;
        const float* b2l  = b2 + (size_t)l * Cn;

        ln_kernel<<<BT, 256>>>(x, ln1g + l * Cn, ln1b + l * Cn, xn);
        gemm_mma<false, false><<<gQKV, 256, GEMM_SMEM>>>(xn, wqkvl, nullptr, nullptr, qkv, C3, Cn);
        attn_flash<<<gAttn, 64>>>(qkv, y);
        gemm_mma<false, false><<<gCC, 256, GEMM_SMEM>>>(y, woRl, bol, x, x, Cn, Cn);

        ln_kernel<<<BT, 256>>>(x, ln2g + l * Cn, ln2b + l * Cn, xn);
        gemm_mma<true, true><<<gCF, 256, GEMM_SMEM>>>(xn, w1Rl, b1l, nullptr, h, Fn, Cn);
        gemm_mma<false, false><<<gCC, 256, GEMM_SMEM>>>(h, w2Rl, b2l, x, x, Cn, Fn);
    }

    ln_kernel<<<BT, 256>>>(x, lnfg, lnfb, xn);
    gemm_mma<false, false><<<gCV, 256, GEMM_SMEM>>>(xn, wlmR, nullptr, nullptr, out, Vn, Cn);
}

// round 7
// speedup vs baseline: 1.5079x; 1.3145x over previous
#include <cuda_runtime.h>
#include <cuda_fp16.h>
#include <cstdint>
#include <math.h>

// GPT forward: B=4, T=512, L=12, C=1024, H=16, HD=64, F=4096, V=32000
#define Bn   4
#define Tn   512
#define Ln   12
#define Cn   1024
#define Hn   16
#define HDn  64
#define Fn   4096
#define Vn   32000
#define BT   (Bn * Tn)          // 2048
#define C3   (3 * Cn)           // 3072

// ---------------- static scratch (no allocations allowed) ----------------
__device__ float  g_x  [BT * Cn];            // residual stream (fp32)
__device__ __half g_xn [BT * Cn];
__device__ __half g_qkv[BT * C3];
__device__ __half g_y  [BT * Cn];
__device__ __half g_h  [BT * Fn];
// fp16 weights; wq/wk/wv packed into [C, 3C] per layer
__device__ __half g_wqkvH[(size_t)Ln * Cn * C3];
__device__ __half g_woH[Ln * Cn * Cn];
__device__ __half g_w1H[Ln * Cn * Fn];
__device__ __half g_w2H[Ln * Fn * Cn];
__device__ __half g_wlmH[(size_t)Vn * Cn];

__device__ __forceinline__ uint32_t smem_u32(const void* p) {
    uint32_t a;
    asm("{ .reg .u64 t; cvta.to.shared.u64 t, %1; cvt.u32.u64 %0, t; }"
        : "=r"(a) : "l"(p));
    return a;
}
__device__ __forceinline__ void cp16(void* s, const void* g) {
    asm volatile("cp.async.cg.shared.global [%0], [%1], 16;"
                 :: "r"(smem_u32(s)), "l"(g) : "memory");
}
#define CP_COMMIT() asm volatile("cp.async.commit_group;" ::: "memory")
#define CP_WAIT1()  asm volatile("cp.async.wait_group 1;" ::: "memory")

// ---------------- one-shot weight rounding / packing to fp16 -------------
#define N_QKVO (Ln * Cn * Cn)          // 12,582,912
#define N_FF   (Ln * Cn * Fn)          // 50,331,648
#define N_LM   ((size_t)Vn * Cn)       // 32,768,000

__global__ void round_weights(const float* wq, const float* wk, const float* wv,
                              const float* wo, const float* w1, const float* w2,
                              const float* wlm,
                              __half* wqkvH, __half* woH,
                              __half* w1H, __half* w2H, __half* wlmH) {
    const float* in; __half* out; size_t n;
    int sel = -1;
    switch (blockIdx.y) {
        case 0: in = wq;  out = wqkvH; n = N_QKVO; sel = 0; break;
        case 1: in = wk;  out = wqkvH; n = N_QKVO; sel = 1; break;
        case 2: in = wv;  out = wqkvH; n = N_QKVO; sel = 2; break;
        case 3: in = wo;  out = woH;  n = N_QKVO; break;
        case 4: in = w1;  out = w1H;  n = N_FF;   break;
        case 5: in = w2;  out = w2H;  n = N_FF;   break;
        default: in = wlm; out = wlmH; n = N_LM;  break;
    }
    size_t i = ((size_t)blockIdx.x * 256 + threadIdx.x) * 8;
    if (i >= n) return;
    float4 v0 = *(const float4*)(in + i);
    float4 v1 = *(const float4*)(in + i + 4);
    __half2 h[4];
    h[0] = __floats2half2_rn(v0.x, v0.y);
    h[1] = __floats2half2_rn(v0.z, v0.w);
    h[2] = __floats2half2_rn(v1.x, v1.y);
    h[3] = __floats2half2_rn(v1.z, v1.w);
    size_t oi = i;
    if (sel >= 0) {
        size_t l = i / (Cn * Cn);
        size_t rem = i - l * Cn * Cn;
        size_t kk = rem / Cn, nn = rem % Cn;
        oi = (l * Cn + kk) * C3 + (size_t)sel * Cn + nn;
    }
    *(uint4*)(out + oi) = *(uint4*)h;
}

// ---------------- embedding (x stays fp32: residual stream) --------------
__global__ void embed_kernel(const int* __restrict__ idx,
                             const float* __restrict__ tok,
                             const float* __restrict__ pos,
                             float* __restrict__ x) {
    int row = blockIdx.x;
    int t = row & (Tn - 1);
    int token = idx[row];
    const float* tp = tok + (size_t)token * Cn;
    const float* pp = pos + (size_t)t * Cn;
    float* xp = x + (size_t)row * Cn;
    for (int c = threadIdx.x; c < Cn; c += 256)
        xp[c] = tp[c] + pp[c];
}

// ---------------- layernorm (fp32 in, fp16 out: feeds GEMM A) ------------
__global__ void ln_kernel(const float* __restrict__ in,
                          const float* __restrict__ g,
                          const float* __restrict__ b,
                          __half* __restrict__ out) {
    int row = blockIdx.x;
    int tid = threadIdx.x;
    const float* p = in + (size_t)row * Cn;
    float s = 0.f, sq = 0.f;
    for (int c = tid; c < Cn; c += 256) { float v = p[c]; s += v; sq += v * v; }
    __shared__ float rs[256], rq[256];
    rs[tid] = s; rq[tid] = sq; __syncthreads();
    for (int o = 128; o > 0; o >>= 1) {
        if (tid < o) { rs[tid] += rs[tid + o]; rq[tid] += rq[tid + o]; }
        __syncthreads();
    }
    float mean = rs[0] * (1.f / Cn);
    float var  = rq[0] * (1.f / Cn) - mean * mean;
    float inv  = rsqrtf(var + 1e-5f);
    __half* op = out + (size_t)row * Cn;
    for (int c = tid; c < Cn; c += 256)
        op[c] = __float2half((p[c] - mean) * inv * g[c] + b[c]);
}

// ---------------- fp16 mma GEMM: C[M,N] = A[M,K] @ B[K,N] ----------------
// CTA 128x128, BK=32 halves, 8 warps (warp tile 64x32), 3-stage cp.async,
// one __syncthreads per chunk, ldmatrix fragment feed, 2 CTAs/SM.
#define APADh 40                        // halves; 80B pitch -> LDSM conflict-free
#define BPADh 136                       // halves; 272B pitch -> conflict-free
#define ASZh  (128 * APADh)             // 5120 halves
#define BSZh  (32 * BPADh)              // 4352 halves
#define STAGEH (ASZh + BSZh)            // 9472 halves
#define GEMM_SMEM (3 * STAGEH * 2)      // 56832 bytes

template<bool RELU, bool OUTH>
__global__ __launch_bounds__(256, 2)
void gemm_h(const __half* __restrict__ A, const __half* __restrict__ B,
            const float* __restrict__ bias, const float* __restrict__ res,
            void* __restrict__ Cout, int N, int K) {
    extern __shared__ __half smh[];
    const int tid = threadIdx.x;
    const int lane = tid & 31, wid = tid >> 5;
    const int warp_m = (wid & 1) << 6;     // 0 or 64
    const int warp_n = (wid >> 1) << 5;    // 0,32,64,96
    const int m0 = blockIdx.y * 128;
    const int n0 = blockIdx.x * 128;

    // load slots: A tile 128x32 halves (2 x16B per thread), B tile 32x128 (2)
    const __half* aptr[2]; const __half* bptr[2];
    int saoff[2], sboff[2];
    #pragma unroll
    for (int j = 0; j < 2; j++) {
        int ia = j * 256 + tid;                    // 0..511
        int ar = ia >> 2, ac = (ia & 3) << 3;      // row 0..127, k 0,8,16,24
        aptr[j] = A + (size_t)(m0 + ar) * K + ac;
        saoff[j] = ar * APADh + ac;
        int bk = ia >> 4, bc = (ia & 15) << 3;     // k 0..31, n 0,8..120
        bptr[j] = B + (size_t)bk * N + n0 + bc;
        sboff[j] = bk * BPADh + bc;
    }

    const int nk = K >> 5;

    #pragma unroll
    for (int s = 0; s < 2; s++) {
        __half* As = smh + s * STAGEH;
        __half* Bs = As + ASZh;
        const int kk = s << 5;
        #pragma unroll
        for (int j = 0; j < 2; j++) {
            cp16(As + saoff[j], aptr[j] + kk);
            cp16(Bs + sboff[j], bptr[j] + (size_t)kk * N);
        }
        CP_COMMIT();
    }

    float acc[4][4][4];
    #pragma unroll
    for (int mi = 0; mi < 4; mi++)
        #pragma unroll
        for (int ni = 0; ni < 4; ni++)
            #pragma unroll
            for (int r = 0; r < 4; r++) acc[mi][ni][r] = 0.f;

    // lane-dependent ldmatrix address pieces
    const int a_i = lane >> 3, a_r = lane & 7;
    const int arow_lane = ((a_i & 1) << 3) + a_r;  // row offset within 16
    const int acol_lane = (a_i >> 1) << 3;         // k offset 0 or 8
    const int b_k = lane & 15;

    int rstage = 0, wstage = 2;
    for (int it = 0; it < nk; ++it) {
        CP_WAIT1();
        __syncthreads();

        const __half* Ac = smh + rstage * STAGEH;
        const __half* Bc = Ac + ASZh;
        #pragma unroll
        for (int ks = 0; ks < 2; ks++) {
            const int kb = ks << 4;
            uint32_t af[4][4], bf[4][2];
            #pragma unroll
            for (int mi = 0; mi < 4; mi++) {
                int row = warp_m + mi * 16 + arow_lane;
                uint32_t ad = smem_u32(Ac + row * APADh + kb + acol_lane);
                asm volatile("ldmatrix.sync.aligned.m8n8.x4.shared.b16 "
                             "{%0,%1,%2,%3}, [%4];"
                             : "=r"(af[mi][0]), "=r"(af[mi][1]),
                               "=r"(af[mi][2]), "=r"(af[mi][3]) : "r"(ad));
            }
            #pragma unroll
            for (int ni = 0; ni < 4; ni++) {
                int colB = warp_n + ni * 8;
                uint32_t bd = smem_u32(Bc + (kb + b_k) * BPADh + colB);
                asm volatile("ldmatrix.sync.aligned.m8n8.x2.trans.shared.b16 "
                             "{%0,%1}, [%2];"
                             : "=r"(bf[ni][0]), "=r"(bf[ni][1]) : "r"(bd));
            }
            #pragma unroll
            for (int mi = 0; mi < 4; mi++)
                #pragma unroll
                for (int ni = 0; ni < 4; ni++) {
                    asm volatile(
                        "mma.sync.aligned.m16n8k16.row.col.f32.f16.f16.f32 "
                        "{%0,%1,%2,%3}, {%4,%5,%6,%7}, {%8,%9}, {%0,%1,%2,%3};"
                        : "+f"(acc[mi][ni][0]), "+f"(acc[mi][ni][1]),
                          "+f"(acc[mi][ni][2]), "+f"(acc[mi][ni][3])
                        : "r"(af[mi][0]), "r"(af[mi][1]), "r"(af[mi][2]), "r"(af[mi][3]),
                          "r"(bf[ni][0]), "r"(bf[ni][1]));
                }
        }

        if (it + 2 < nk) {
            const int kk = (it + 2) << 5;
            __half* As = smh + wstage * STAGEH;
            __half* Bs = As + ASZh;
            #pragma unroll
            for (int j = 0; j < 2; j++) {
                cp16(As + saoff[j], aptr[j] + kk);
                cp16(Bs + sboff[j], bptr[j] + (size_t)kk * N);
            }
        }
        CP_COMMIT();

        rstage = (rstage == 2) ? 0 : rstage + 1;
        wstage = (wstage == 2) ? 0 : wstage + 1;
    }

    // epilogue
    #pragma unroll
    for (int mi = 0; mi < 4; mi++) {
        int row = m0 + warp_m + mi * 16 + (lane >> 2);
        #pragma unroll
        for (int ni = 0; ni < 4; ni++) {
            int col = n0 + warp_n + ni * 8 + ((lane & 3) << 1);
            float v0 = acc[mi][ni][0], v1 = acc[mi][ni][1];
            float v2 = acc[mi][ni][2], v3 = acc[mi][ni][3];
            if (bias) {
                float b0 = bias[col], b1 = bias[col + 1];
                v0 += b0; v1 += b1; v2 += b0; v3 += b1;
            }
            if (RELU) {
                v0 = fmaxf(v0, 0.f); v1 = fmaxf(v1, 0.f);
                v2 = fmaxf(v2, 0.f); v3 = fmaxf(v3, 0.f);
            }
            if (OUTH) {
                __half* Cp = (__half*)Cout;
                *(__half2*)(Cp + (size_t)row * N + col) = __floats2half2_rn(v0, v1);
                *(__half2*)(Cp + (size_t)(row + 8) * N + col) = __floats2half2_rn(v2, v3);
            } else {
                float* Cp = (float*)Cout;
                if (res) {
                    const float2 r0 = *(const float2*)(res + (size_t)row * N + col);
                    const float2 r1 = *(const float2*)(res + (size_t)(row + 8) * N + col);
                    v0 += r0.x; v1 += r0.y; v2 += r1.x; v3 += r1.y;
                }
                *(float2*)(Cp + (size_t)row * N + col) = make_float2(v0, v1);
                *(float2*)(Cp + (size_t)(row + 8) * N + col) = make_float2(v2, v3);
            }
        }
    }
}

// ---------------- flash attention, single QK pass, strip-mined softmax ---
__global__ __launch_bounds__(64)
void attn_flash(const __half* __restrict__ qkv, __half* __restrict__ y) {
    const int tt = blockIdx.x, h = blockIdx.y, b = blockIdx.z;
    const int tid = threadIdx.x;
    __shared__ __align__(16) float ks[64 * 64];
    __shared__ __align__(16) float vs[64 * 64];
    const size_t base = (size_t)b * Tn * C3 + (size_t)h * HDn;
    const int t0 = tt * 64;

    for (int i = tid; i < 4096; i += 64)
        ks[i] = __half2float(qkv[base + (size_t)(t0 + (i >> 6)) * C3 + (i & 63)]);
    __syncthreads();
    float qr[64];
    #pragma unroll
    for (int d = 0; d < 64; d++) qr[d] = ks[tid * 64 + d] * 0.125f;
    __syncthreads();

    float m = -1e30f, l = 0.f;
    float acc[64];
    #pragma unroll
    for (int d = 0; d < 64; d++) acc[d] = 0.f;

    for (int st = 0; st <= tt; ++st) {
        const int s0 = st * 64;
        for (int i = tid; i < 4096; i += 64) {
            size_t gi = base + (size_t)(s0 + (i >> 6)) * C3 + (i & 63);
            ks[i] = __half2float(qkv[gi + Cn]);      // K
            vs[i] = __half2float(qkv[gi + 2 * Cn]);  // V
        }
        __syncthreads();
        const int smax = (st == tt) ? tid : 63;

        for (int ss = 0; ss <= smax; ss += 16) {
            float dd[16];
            float tm = -1e30f;
            #pragma unroll
            for (int i = 0; i < 16; i++) {
                const int s = ss + i;
                const float4* kp = (const float4*)(ks + s * 64);
                float d = 0.f;
                #pragma unroll
                for (int j = 0; j < 16; j++) {
                    float4 kv = kp[j];
                    d += qr[4*j] * kv.x + qr[4*j+1] * kv.y
                       + qr[4*j+2] * kv.z + qr[4*j+3] * kv.w;
                }
                d = (s <= smax) ? d : -1e30f;
                dd[i] = d;
                tm = fmaxf(tm, d);
            }
            if (tm > m) {
                float scl = __expf(m - tm);
                l *= scl;
                #pragma unroll
                for (int d = 0; d < 64; d++) acc[d] *= scl;
                m = tm;
            }
            #pragma unroll
            for (int i = 0; i < 16; i++) {
                const int s = ss + i;
                float p = (s <= smax) ? __expf(dd[i] - m) : 0.f;
                l += p;
                const float4* vp = (const float4*)(vs + s * 64);
                #pragma unroll
                for (int j = 0; j < 16; j++) {
                    float4 vv = vp[j];
                    acc[4*j]   += p * vv.x; acc[4*j+1] += p * vv.y;
                    acc[4*j+2] += p * vv.z; acc[4*j+3] += p * vv.w;
                }
            }
        }
        __syncthreads();
    }

    const float inv = 1.f / l;
    #pragma unroll
    for (int d = 0; d < 64; d++) ks[tid * 64 + d] = acc[d] * inv;
    __syncthreads();
    const size_t ybase = (size_t)b * Tn * Cn + (size_t)h * HDn;
    for (int i = tid; i < 4096; i += 64)
        y[ybase + (size_t)(t0 + (i >> 6)) * Cn + (i & 63)] = __float2half(ks[i]);
}

// ---------------- launch ----------------
extern "C" void kernel_launch(void* const* d_in, const int* in_sizes, int n_in,
                              void* d_out, int out_size) {
    const int*   idx   = (const int*)  d_in[0];
    const float* tok   = (const float*)d_in[1];
    const float* pos   = (const float*)d_in[2];
    const float* wq    = (const float*)d_in[3];
    const float* wk    = (const float*)d_in[4];
    const float* wv    = (const float*)d_in[5];
    const float* wo    = (const float*)d_in[6];
    const float* bo    = (const float*)d_in[7];
    const float* ln1g  = (const float*)d_in[8];
    const float* ln1b  = (const float*)d_in[9];
    const float* ln2g  = (const float*)d_in[10];
    const float* ln2b  = (const float*)d_in[11];
    const float* w1    = (const float*)d_in[12];
    const float* b1    = (const float*)d_in[13];
    const float* w2    = (const float*)d_in[14];
    const float* b2    = (const float*)d_in[15];
    const float* lnfg  = (const float*)d_in[16];
    const float* lnfb  = (const float*)d_in[17];
    const float* wlm   = (const float*)d_in[18];
    float* out = (float*)d_out;

    float *x;
    __half *xn, *qkv, *y, *h;
    __half *wqkvH, *woH, *w1H, *w2H, *wlmH;
    cudaGetSymbolAddress((void**)&x,   g_x);
    cudaGetSymbolAddress((void**)&xn,  g_xn);
    cudaGetSymbolAddress((void**)&qkv, g_qkv);
    cudaGetSymbolAddress((void**)&y,   g_y);
    cudaGetSymbolAddress((void**)&h,   g_h);
    cudaGetSymbolAddress((void**)&wqkvH, g_wqkvH);
    cudaGetSymbolAddress((void**)&woH, g_woH);
    cudaGetSymbolAddress((void**)&w1H, g_w1H);
    cudaGetSymbolAddress((void**)&w2H, g_w2H);
    cudaGetSymbolAddress((void**)&wlmH, g_wlmH);

    cudaFuncSetAttribute(gemm_h<false, true>,
                         cudaFuncAttributeMaxDynamicSharedMemorySize, GEMM_SMEM);
    cudaFuncSetAttribute(gemm_h<true, true>,
                         cudaFuncAttributeMaxDynamicSharedMemorySize, GEMM_SMEM);
    cudaFuncSetAttribute(gemm_h<false, false>,
                         cudaFuncAttributeMaxDynamicSharedMemorySize, GEMM_SMEM);

    // launch 0: round+pack all weights to fp16
    round_weights<<<dim3(N_FF / 8 / 256, 7), 256>>>(
        wq, wk, wv, wo, w1, w2, wlm, wqkvH, woH, w1H, w2H, wlmH);
    // launch 1
    embed_kernel<<<BT, 256>>>(idx, tok, pos, x);

    const dim3 gQKV(C3 / 128, BT / 128);   // 24 x 16 = 384
    const dim3 gCC(Cn / 128, BT / 128);    // 8 x 16 = 128
    const dim3 gCF(Fn / 128, BT / 128);    // 32 x 16 = 512
    const dim3 gCV(Vn / 128, BT / 128);    // 250 x 16
    const dim3 gAttn(Tn / 64, Hn, Bn);     // 8 x 16 x 4

    for (int l = 0; l < Ln; l++) {
        const __half* wqkvl = wqkvH + (size_t)l * Cn * C3;
        const __half* woHl = woH + (size_t)l * Cn * Cn;
        const float* bol  = bo + (size_t)l * Cn;
        const __half* w1Hl = w1H + (size_t)l * Cn * Fn;
        const float* b1l  = b1 + (size_t)l * Fn;
        const __half* w2Hl = w2H + (size_t)l * Fn * Cn;
        const float* b2l  = b2 + (size_t)l * Cn;

        ln_kernel<<<BT, 256>>>(x, ln1g + l * Cn, ln1b + l * Cn, xn);
        gemm_h<false, true><<<gQKV, 256, GEMM_SMEM>>>(xn, wqkvl, nullptr, nullptr, qkv, C3, Cn);
        attn_flash<<<gAttn, 64>>>(qkv, y);
        gemm_h<false, false><<<gCC, 256, GEMM_SMEM>>>(y, woHl, bol, x, x, Cn, Cn);

        ln_kernel<<<BT, 256>>>(x, ln2g + l * Cn, ln2b + l * Cn, xn);
        gemm_h<true, true><<<gCF, 256, GEMM_SMEM>>>(xn, w1Hl, b1l, nullptr, h, Fn, Cn);
        gemm_h<false, false><<<gCC, 256, GEMM_SMEM>>>(h, w2Hl, b2l, x, x, Cn, Fn);
    }

    ln_kernel<<<BT, 256>>>(x, lnfg, lnfb, xn);
    gemm_h<false, false><<<gCV, 256, GEMM_SMEM>>>(xn, wlmH, nullptr, nullptr, out, Vn, Cn);
}

// round 8
// speedup vs baseline: 1.5444x; 1.0242x over previous
#include <cuda_runtime.h>
#include <cuda_fp16.h>
#include <cstdint>
#include <math.h>

// GPT forward: B=4, T=512, L=12, C=1024, H=16, HD=64, F=4096, V=32000
#define Bn   4
#define Tn   512
#define Ln   12
#define Cn   1024
#define Hn   16
#define HDn  64
#define Fn   4096
#define Vn   32000
#define BT   (Bn * Tn)          // 2048
#define C3   (3 * Cn)           // 3072

// ---------------- static scratch (no allocations allowed) ----------------
__device__ float  g_x  [BT * Cn];            // residual stream (fp32)
__device__ __half g_xn [BT * Cn];
__device__ __half g_qkv[BT * C3];
__device__ __half g_y  [BT * Cn];
__device__ __half g_h  [BT * Fn];
// fp16 weights; wq/wk/wv packed into [C, 3C] per layer
__device__ __half g_wqkvH[(size_t)Ln * Cn * C3];
__device__ __half g_woH[Ln * Cn * Cn];
__device__ __half g_w1H[Ln * Cn * Fn];
__device__ __half g_w2H[Ln * Fn * Cn];
__device__ __half g_wlmH[(size_t)Vn * Cn];

__device__ __forceinline__ uint32_t smem_u32(const void* p) {
    uint32_t a;
    asm("{ .reg .u64 t; cvta.to.shared.u64 t, %1; cvt.u32.u64 %0, t; }"
        : "=r"(a) : "l"(p));
    return a;
}
__device__ __forceinline__ void cp16(void* s, const void* g) {
    asm volatile("cp.async.cg.shared.global [%0], [%1], 16;"
                 :: "r"(smem_u32(s)), "l"(g) : "memory");
}
#define CP_COMMIT() asm volatile("cp.async.commit_group;" ::: "memory")
#define CP_WAIT2()  asm volatile("cp.async.wait_group 2;" ::: "memory")

// ---------------- one-shot weight rounding / packing to fp16 -------------
#define N_QKVO (Ln * Cn * Cn)          // 12,582,912
#define N_FF   (Ln * Cn * Fn)          // 50,331,648
#define N_LM   ((size_t)Vn * Cn)       // 32,768,000

__global__ void round_weights(const float* wq, const float* wk, const float* wv,
                              const float* wo, const float* w1, const float* w2,
                              const float* wlm,
                              __half* wqkvH, __half* woH,
                              __half* w1H, __half* w2H, __half* wlmH) {
    const float* in; __half* out; size_t n;
    int sel = -1;
    switch (blockIdx.y) {
        case 0: in = wq;  out = wqkvH; n = N_QKVO; sel = 0; break;
        case 1: in = wk;  out = wqkvH; n = N_QKVO; sel = 1; break;
        case 2: in = wv;  out = wqkvH; n = N_QKVO; sel = 2; break;
        case 3: in = wo;  out = woH;  n = N_QKVO; break;
        case 4: in = w1;  out = w1H;  n = N_FF;   break;
        case 5: in = w2;  out = w2H;  n = N_FF;   break;
        default: in = wlm; out = wlmH; n = N_LM;  break;
    }
    size_t i = ((size_t)blockIdx.x * 256 + threadIdx.x) * 8;
    if (i >= n) return;
    float4 v0 = *(const float4*)(in + i);
    float4 v1 = *(const float4*)(in + i + 4);
    __half2 h[4];
    h[0] = __floats2half2_rn(v0.x, v0.y);
    h[1] = __floats2half2_rn(v0.z, v0.w);
    h[2] = __floats2half2_rn(v1.x, v1.y);
    h[3] = __floats2half2_rn(v1.z, v1.w);
    size_t oi = i;
    if (sel >= 0) {
        size_t l = i / (Cn * Cn);
        size_t rem = i - l * Cn * Cn;
        size_t kk = rem / Cn, nn = rem % Cn;
        oi = (l * Cn + kk) * C3 + (size_t)sel * Cn + nn;
    }
    *(uint4*)(out + oi) = *(uint4*)h;
}

// ---------------- embedding (x stays fp32: residual stream) --------------
__global__ void embed_kernel(const int* __restrict__ idx,
                             const float* __restrict__ tok,
                             const float* __restrict__ pos,
                             float* __restrict__ x) {
    int row = blockIdx.x;
    int t = row & (Tn - 1);
    int token = idx[row];
    const float* tp = tok + (size_t)token * Cn;
    const float* pp = pos + (size_t)t * Cn;
    float* xp = x + (size_t)row * Cn;
    for (int c = threadIdx.x; c < Cn; c += 256)
        xp[c] = tp[c] + pp[c];
}

// ---------------- layernorm (fp32 in, fp16 out: feeds GEMM A) ------------
__global__ void ln_kernel(const float* __restrict__ in,
                          const float* __restrict__ g,
                          const float* __restrict__ b,
                          __half* __restrict__ out) {
    int row = blockIdx.x;
    int tid = threadIdx.x;
    const float* p = in + (size_t)row * Cn;
    float s = 0.f, sq = 0.f;
    for (int c = tid; c < Cn; c += 256) { float v = p[c]; s += v; sq += v * v; }
    __shared__ float rs[256], rq[256];
    rs[tid] = s; rq[tid] = sq; __syncthreads();
    for (int o = 128; o > 0; o >>= 1) {
        if (tid < o) { rs[tid] += rs[tid + o]; rq[tid] += rq[tid + o]; }
        __syncthreads();
    }
    float mean = rs[0] * (1.f / Cn);
    float var  = rq[0] * (1.f / Cn) - mean * mean;
    float inv  = rsqrtf(var + 1e-5f);
    __half* op = out + (size_t)row * Cn;
    for (int c = tid; c < Cn; c += 256)
        op[c] = __float2half((p[c] - mean) * inv * g[c] + b[c]);
}

// ---------------- fp16 mma GEMM: C[M,N] = A[M,K] @ B[K,N] ----------------
// CTA 128x128, BK=32 halves, 8 warps (warp tile 64x32), 4-stage cp.async,
// one __syncthreads per chunk, ldmatrix feed, 2 CTAs/SM.
// gridDim.z = split-K factor; ATOMIC epilogue accumulates into fp32 C.
#define APADh 40                        // halves; 80B pitch -> LDSM conflict-free
#define BPADh 136                       // halves; 272B pitch -> conflict-free
#define ASZh  (128 * APADh)             // 5120 halves
#define BSZh  (32 * BPADh)              // 4352 halves
#define STAGEH (ASZh + BSZh)            // 9472 halves
#define GEMM_SMEM (4 * STAGEH * 2)      // 75776 bytes

template<bool RELU, bool OUTH, bool ATOMIC>
__global__ __launch_bounds__(256, 2)
void gemm_h(const __half* __restrict__ A, const __half* __restrict__ B,
            const float* __restrict__ bias, const float* __restrict__ res,
            void* __restrict__ Cout, int N, int K) {
    extern __shared__ __half smh[];
    const int tid = threadIdx.x;
    const int lane = tid & 31, wid = tid >> 5;
    const int warp_m = (wid & 1) << 6;     // 0 or 64
    const int warp_n = (wid >> 1) << 5;    // 0,32,64,96
    const int m0 = blockIdx.y * 128;
    const int n0 = blockIdx.x * 128;
    const int Ksub = K / gridDim.z;
    const int koff = blockIdx.z * Ksub;

    const __half* aptr[2]; const __half* bptr[2];
    int saoff[2], sboff[2];
    #pragma unroll
    for (int j = 0; j < 2; j++) {
        int ia = j * 256 + tid;                    // 0..511
        int ar = ia >> 2, ac = (ia & 3) << 3;      // row 0..127, k 0,8,16,24
        aptr[j] = A + (size_t)(m0 + ar) * K + koff + ac;
        saoff[j] = ar * APADh + ac;
        int bk = ia >> 4, bc = (ia & 15) << 3;     // k 0..31, n 0,8..120
        bptr[j] = B + (size_t)(koff + bk) * N + n0 + bc;
        sboff[j] = bk * BPADh + bc;
    }

    const int nk = Ksub >> 5;                      // >= 16 always

    // prologue: stages 0..2
    #pragma unroll
    for (int s = 0; s < 3; s++) {
        __half* As = smh + s * STAGEH;
        __half* Bs = As + ASZh;
        const int kk = s << 5;
        #pragma unroll
        for (int j = 0; j < 2; j++) {
            cp16(As + saoff[j], aptr[j] + kk);
            cp16(Bs + sboff[j], bptr[j] + (size_t)kk * N);
        }
        CP_COMMIT();
    }

    float acc[4][4][4];
    #pragma unroll
    for (int mi = 0; mi < 4; mi++)
        #pragma unroll
        for (int ni = 0; ni < 4; ni++)
            #pragma unroll
            for (int r = 0; r < 4; r++) acc[mi][ni][r] = 0.f;

    const int a_i = lane >> 3, a_r = lane & 7;
    const int arow_lane = ((a_i & 1) << 3) + a_r;
    const int acol_lane = (a_i >> 1) << 3;
    const int b_k = lane & 15;

    for (int it = 0; it < nk; ++it) {
        CP_WAIT2();
        __syncthreads();

        const __half* Ac = smh + (it & 3) * STAGEH;
        const __half* Bc = Ac + ASZh;
        #pragma unroll
        for (int ks = 0; ks < 2; ks++) {
            const int kb = ks << 4;
            uint32_t af[4][4], bf[4][2];
            #pragma unroll
            for (int mi = 0; mi < 4; mi++) {
                int row = warp_m + mi * 16 + arow_lane;
                uint32_t ad = smem_u32(Ac + row * APADh + kb + acol_lane);
                asm volatile("ldmatrix.sync.aligned.m8n8.x4.shared.b16 "
                             "{%0,%1,%2,%3}, [%4];"
                             : "=r"(af[mi][0]), "=r"(af[mi][1]),
                               "=r"(af[mi][2]), "=r"(af[mi][3]) : "r"(ad));
            }
            #pragma unroll
            for (int ni = 0; ni < 4; ni++) {
                int colB = warp_n + ni * 8;
                uint32_t bd = smem_u32(Bc + (kb + b_k) * BPADh + colB);
                asm volatile("ldmatrix.sync.aligned.m8n8.x2.trans.shared.b16 "
                             "{%0,%1}, [%2];"
                             : "=r"(bf[ni][0]), "=r"(bf[ni][1]) : "r"(bd));
            }
            #pragma unroll
            for (int mi = 0; mi < 4; mi++)
                #pragma unroll
                for (int ni = 0; ni < 4; ni++) {
                    asm volatile(
                        "mma.sync.aligned.m16n8k16.row.col.f32.f16.f16.f32 "
                        "{%0,%1,%2,%3}, {%4,%5,%6,%7}, {%8,%9}, {%0,%1,%2,%3};"
                        : "+f"(acc[mi][ni][0]), "+f"(acc[mi][ni][1]),
                          "+f"(acc[mi][ni][2]), "+f"(acc[mi][ni][3])
                        : "r"(af[mi][0]), "r"(af[mi][1]), "r"(af[mi][2]), "r"(af[mi][3]),
                          "r"(bf[ni][0]), "r"(bf[ni][1]));
                }
        }

        if (it + 3 < nk) {
            const int kk = (it + 3) << 5;
            __half* As = smh + ((it + 3) & 3) * STAGEH;
            __half* Bs = As + ASZh;
            #pragma unroll
            for (int j = 0; j < 2; j++) {
                cp16(As + saoff[j], aptr[j] + kk);
                cp16(Bs + sboff[j], bptr[j] + (size_t)kk * N);
            }
        }
        CP_COMMIT();
    }

    // epilogue
    const bool addb = (bias != nullptr) && (!ATOMIC || blockIdx.z == 0);
    #pragma unroll
    for (int mi = 0; mi < 4; mi++) {
        int row = m0 + warp_m + mi * 16 + (lane >> 2);
        #pragma unroll
        for (int ni = 0; ni < 4; ni++) {
            int col = n0 + warp_n + ni * 8 + ((lane & 3) << 1);
            float v0 = acc[mi][ni][0], v1 = acc[mi][ni][1];
            float v2 = acc[mi][ni][2], v3 = acc[mi][ni][3];
            if (addb) {
                float b0 = bias[col], b1 = bias[col + 1];
                v0 += b0; v1 += b1; v2 += b0; v3 += b1;
            }
            if (RELU) {
                v0 = fmaxf(v0, 0.f); v1 = fmaxf(v1, 0.f);
                v2 = fmaxf(v2, 0.f); v3 = fmaxf(v3, 0.f);
            }
            if (ATOMIC) {
                float* Cp = (float*)Cout;
                atomicAdd(Cp + (size_t)row * N + col,       v0);
                atomicAdd(Cp + (size_t)row * N + col + 1,   v1);
                atomicAdd(Cp + (size_t)(row + 8) * N + col,     v2);
                atomicAdd(Cp + (size_t)(row + 8) * N + col + 1, v3);
            } else if (OUTH) {
                __half* Cp = (__half*)Cout;
                *(__half2*)(Cp + (size_t)row * N + col) = __floats2half2_rn(v0, v1);
                *(__half2*)(Cp + (size_t)(row + 8) * N + col) = __floats2half2_rn(v2, v3);
            } else {
                float* Cp = (float*)Cout;
                if (res) {
                    const float2 r0 = *(const float2*)(res + (size_t)row * N + col);
                    const float2 r1 = *(const float2*)(res + (size_t)(row + 8) * N + col);
                    v0 += r0.x; v1 += r0.y; v2 += r1.x; v3 += r1.y;
                }
                *(float2*)(Cp + (size_t)row * N + col) = make_float2(v0, v1);
                *(float2*)(Cp + (size_t)(row + 8) * N + col) = make_float2(v2, v3);
            }
        }
    }
}

// ---------------- flash attention, single QK pass, strip-mined softmax ---
__global__ __launch_bounds__(64)
void attn_flash(const __half* __restrict__ qkv, __half* __restrict__ y) {
    const int tt = blockIdx.x, h = blockIdx.y, b = blockIdx.z;
    const int tid = threadIdx.x;
    __shared__ __align__(16) float ks[64 * 64];
    __shared__ __align__(16) float vs[64 * 64];
    const size_t base = (size_t)b * Tn * C3 + (size_t)h * HDn;
    const int t0 = tt * 64;

    for (int i = tid; i < 4096; i += 64)
        ks[i] = __half2float(qkv[base + (size_t)(t0 + (i >> 6)) * C3 + (i & 63)]);
    __syncthreads();
    float qr[64];
    #pragma unroll
    for (int d = 0; d < 64; d++) qr[d] = ks[tid * 64 + d] * 0.125f;
    __syncthreads();

    float m = -1e30f, l = 0.f;
    float acc[64];
    #pragma unroll
    for (int d = 0; d < 64; d++) acc[d] = 0.f;

    for (int st = 0; st <= tt; ++st) {
        const int s0 = st * 64;
        for (int i = tid; i < 4096; i += 64) {
            size_t gi = base + (size_t)(s0 + (i >> 6)) * C3 + (i & 63);
            ks[i] = __half2float(qkv[gi + Cn]);      // K
            vs[i] = __half2float(qkv[gi + 2 * Cn]);  // V
        }
        __syncthreads();
        const int smax = (st == tt) ? tid : 63;

        for (int ss = 0; ss <= smax; ss += 16) {
            float dd[16];
            float tm = -1e30f;
            #pragma unroll
            for (int i = 0; i < 16; i++) {
                const int s = ss + i;
                const float4* kp = (const float4*)(ks + s * 64);
                float d = 0.f;
                #pragma unroll
                for (int j = 0; j < 16; j++) {
                    float4 kv = kp[j];
                    d += qr[4*j] * kv.x + qr[4*j+1] * kv.y
                       + qr[4*j+2] * kv.z + qr[4*j+3] * kv.w;
                }
                d = (s <= smax) ? d : -1e30f;
                dd[i] = d;
                tm = fmaxf(tm, d);
            }
            if (tm > m) {
                float scl = __expf(m - tm);
                l *= scl;
                #pragma unroll
                for (int d = 0; d < 64; d++) acc[d] *= scl;
                m = tm;
            }
            #pragma unroll
            for (int i = 0; i < 16; i++) {
                const int s = ss + i;
                float p = (s <= smax) ? __expf(dd[i] - m) : 0.f;
                l += p;
                const float4* vp = (const float4*)(vs + s * 64);
                #pragma unroll
                for (int j = 0; j < 16; j++) {
                    float4 vv = vp[j];
                    acc[4*j]   += p * vv.x; acc[4*j+1] += p * vv.y;
                    acc[4*j+2] += p * vv.z; acc[4*j+3] += p * vv.w;
                }
            }
        }
        __syncthreads();
    }

    const float inv = 1.f / l;
    #pragma unroll
    for (int d = 0; d < 64; d++) ks[tid * 64 + d] = acc[d] * inv;
    __syncthreads();
    const size_t ybase = (size_t)b * Tn * Cn + (size_t)h * HDn;
    for (int i = tid; i < 4096; i += 64)
        y[ybase + (size_t)(t0 + (i >> 6)) * Cn + (i & 63)] = __float2half(ks[i]);
}

// ---------------- launch ----------------
extern "C" void kernel_launch(void* const* d_in, const int* in_sizes, int n_in,
                              void* d_out, int out_size) {
    const int*   idx   = (const int*)  d_in[0];
    const float* tok   = (const float*)d_in[1];
    const float* pos   = (const float*)d_in[2];
    const float* wq    = (const float*)d_in[3];
    const float* wk    = (const float*)d_in[4];
    const float* wv    = (const float*)d_in[5];
    const float* wo    = (const float*)d_in[6];
    const float* bo    = (const float*)d_in[7];
    const float* ln1g  = (const float*)d_in[8];
    const float* ln1b  = (const float*)d_in[9];
    const float* ln2g  = (const float*)d_in[10];
    const float* ln2b  = (const float*)d_in[11];
    const float* w1    = (const float*)d_in[12];
    const float* b1    = (const float*)d_in[13];
    const float* w2    = (const float*)d_in[14];
    const float* b2    = (const float*)d_in[15];
    const float* lnfg  = (const float*)d_in[16];
    const float* lnfb  = (const float*)d_in[17];
    const float* wlm   = (const float*)d_in[18];
    float* out = (float*)d_out;

    float *x;
    __half *xn, *qkv, *y, *h;
    __half *wqkvH, *woH, *w1H, *w2H, *wlmH;
    cudaGetSymbolAddress((void**)&x,   g_x);
    cudaGetSymbolAddress((void**)&xn,  g_xn);
    cudaGetSymbolAddress((void**)&qkv, g_qkv);
    cudaGetSymbolAddress((void**)&y,   g_y);
    cudaGetSymbolAddress((void**)&h,   g_h);
    cudaGetSymbolAddress((void**)&wqkvH, g_wqkvH);
    cudaGetSymbolAddress((void**)&woH, g_woH);
    cudaGetSymbolAddress((void**)&w1H, g_w1H);
    cudaGetSymbolAddress((void**)&w2H, g_w2H);
    cudaGetSymbolAddress((void**)&wlmH, g_wlmH);

    cudaFuncSetAttribute(gemm_h<false, true, false>,
                         cudaFuncAttributeMaxDynamicSharedMemorySize, GEMM_SMEM);
    cudaFuncSetAttribute(gemm_h<true, true, false>,
                         cudaFuncAttributeMaxDynamicSharedMemorySize, GEMM_SMEM);
    cudaFuncSetAttribute(gemm_h<false, false, false>,
                         cudaFuncAttributeMaxDynamicSharedMemorySize, GEMM_SMEM);
    cudaFuncSetAttribute(gemm_h<false, false, true>,
                         cudaFuncAttributeMaxDynamicSharedMemorySize, GEMM_SMEM);

    // launch 0: round+pack all weights to fp16
    round_weights<<<dim3(N_FF / 8 / 256, 7), 256>>>(
        wq, wk, wv, wo, w1, w2, wlm, wqkvH, woH, w1H, w2H, wlmH);
    // launch 1
    embed_kernel<<<BT, 256>>>(idx, tok, pos, x);

    const dim3 gQKV(C3 / 128, BT / 128);       // 24 x 16 = 384
    const dim3 gCCs(Cn / 128, BT / 128, 2);    // 8 x 16 x 2 = 256 (split-K)
    const dim3 gCF(Fn / 128, BT / 128);        // 32 x 16 = 512
    const dim3 gCV(Vn / 128, BT / 128);        // 250 x 16
    const dim3 gAttn(Tn / 64, Hn, Bn);         // 8 x 16 x 4

    for (int l = 0; l < Ln; l++) {
        const __half* wqkvl = wqkvH + (size_t)l * Cn * C3;
        const __half* woHl = woH + (size_t)l * Cn * Cn;
        const float* bol  = bo + (size_t)l * Cn;
        const __half* w1Hl = w1H + (size_t)l * Cn * Fn;
        const float* b1l  = b1 + (size_t)l * Fn;
        const __half* w2Hl = w2H + (size_t)l * Fn * Cn;
        const float* b2l  = b2 + (size_t)l * Cn;

        ln_kernel<<<BT, 256>>>(x, ln1g + l * Cn, ln1b + l * Cn, xn);
        gemm_h<false, true, false><<<gQKV, 256, GEMM_SMEM>>>(xn, wqkvl, nullptr, nullptr, qkv, C3, Cn);
        attn_flash<<<gAttn, 64>>>(qkv, y);
        // split-K=2, atomic accumulate into residual x (dst == res)
        gemm_h<false, false, true><<<gCCs, 256, GEMM_SMEM>>>(y, woHl, bol, nullptr, x, Cn, Cn);

        ln_kernel<<<BT, 256>>>(x, ln2g + l * Cn, ln2b + l * Cn, xn);
        gemm_h<true, true, false><<<gCF, 256, GEMM_SMEM>>>(xn, w1Hl, b1l, nullptr, h, Fn, Cn);
        gemm_h<false, false, true><<<gCCs, 256, GEMM_SMEM>>>(h, w2Hl, b2l, nullptr, x, Cn, Fn);
    }

    ln_kernel<<<BT, 256>>>(x, lnfg, lnfb, xn);
    gemm_h<false, false, false><<<gCV, 256, GEMM_SMEM>>>(xn, wlmH, nullptr, nullptr, out, Vn, Cn);
}

// round 9
// speedup vs baseline: 2.7324x; 1.7692x over previous
#include <cuda_runtime.h>
#include <cuda_fp16.h>
#include <cstdint>
#include <math.h>

// GPT forward: B=4, T=512, L=12, C=1024, H=16, HD=64, F=4096, V=32000
#define Bn   4
#define Tn   512
#define Ln   12
#define Cn   1024
#define Hn   16
#define HDn  64
#define Fn   4096
#define Vn   32000
#define BT   (Bn * Tn)          // 2048
#define C3   (3 * Cn)           // 3072

// ---------------- static scratch (no allocations allowed) ----------------
__device__ float  g_x  [BT * Cn];            // residual stream (fp32)
__device__ __half g_xn [BT * Cn];
__device__ __half g_qkv[BT * C3];
__device__ __half g_y  [BT * Cn];
__device__ __half g_h  [BT * Fn];
// fp16 weights; wq/wk/wv packed into [C, 3C] per layer
__device__ __half g_wqkvH[(size_t)Ln * Cn * C3];
__device__ __half g_woH[Ln * Cn * Cn];
__device__ __half g_w1H[Ln * Cn * Fn];
__device__ __half g_w2H[Ln * Fn * Cn];
__device__ __half g_wlmH[(size_t)Vn * Cn];

__device__ __forceinline__ uint32_t smem_u32(const void* p) {
    uint32_t a;
    asm("{ .reg .u64 t; cvta.to.shared.u64 t, %1; cvt.u32.u64 %0, t; }"
        : "=r"(a) : "l"(p));
    return a;
}
__device__ __forceinline__ void cp16(void* s, const void* g) {
    asm volatile("cp.async.cg.shared.global [%0], [%1], 16;"
                 :: "r"(smem_u32(s)), "l"(g) : "memory");
}
#define CP_COMMIT() asm volatile("cp.async.commit_group;" ::: "memory")
#define CP_WAIT2()  asm volatile("cp.async.wait_group 2;" ::: "memory")

#define MMA_F16(acc, a, b0, b1) \
    asm volatile( \
        "mma.sync.aligned.m16n8k16.row.col.f32.f16.f16.f32 " \
        "{%0,%1,%2,%3}, {%4,%5,%6,%7}, {%8,%9}, {%0,%1,%2,%3};" \
        : "+f"((acc)[0]), "+f"((acc)[1]), "+f"((acc)[2]), "+f"((acc)[3]) \
        : "r"((a)[0]), "r"((a)[1]), "r"((a)[2]), "r"((a)[3]), \
          "r"(b0), "r"(b1))

// ---------------- one-shot weight rounding / packing to fp16 -------------
#define N_QKVO (Ln * Cn * Cn)          // 12,582,912
#define N_FF   (Ln * Cn * Fn)          // 50,331,648
#define N_LM   ((size_t)Vn * Cn)       // 32,768,000

__global__ void round_weights(const float* wq, const float* wk, const float* wv,
                              const float* wo, const float* w1, const float* w2,
                              const float* wlm,
                              __half* wqkvH, __half* woH,
                              __half* w1H, __half* w2H, __half* wlmH) {
    const float* in; __half* out; size_t n;
    int sel = -1;
    switch (blockIdx.y) {
        case 0: in = wq;  out = wqkvH; n = N_QKVO; sel = 0; break;
        case 1: in = wk;  out = wqkvH; n = N_QKVO; sel = 1; break;
        case 2: in = wv;  out = wqkvH; n = N_QKVO; sel = 2; break;
        case 3: in = wo;  out = woH;  n = N_QKVO; break;
        case 4: in = w1;  out = w1H;  n = N_FF;   break;
        case 5: in = w2;  out = w2H;  n = N_FF;   break;
        default: in = wlm; out = wlmH; n = N_LM;  break;
    }
    size_t i = ((size_t)blockIdx.x * 256 + threadIdx.x) * 8;
    if (i >= n) return;
    float4 v0 = *(const float4*)(in + i);
    float4 v1 = *(const float4*)(in + i + 4);
    __half2 h[4];
    h[0] = __floats2half2_rn(v0.x, v0.y);
    h[1] = __floats2half2_rn(v0.z, v0.w);
    h[2] = __floats2half2_rn(v1.x, v1.y);
    h[3] = __floats2half2_rn(v1.z, v1.w);
    size_t oi = i;
    if (sel >= 0) {
        size_t l = i / (Cn * Cn);
        size_t rem = i - l * Cn * Cn;
        size_t kk = rem / Cn, nn = rem % Cn;
        oi = (l * Cn + kk) * C3 + (size_t)sel * Cn + nn;
    }
    *(uint4*)(out + oi) = *(uint4*)h;
}

// ---------------- embedding (x stays fp32: residual stream) --------------
__global__ void embed_kernel(const int* __restrict__ idx,
                             const float* __restrict__ tok,
                             const float* __restrict__ pos,
                             float* __restrict__ x) {
    int row = blockIdx.x;
    int t = row & (Tn - 1);
    int token = idx[row];
    const float* tp = tok + (size_t)token * Cn;
    const float* pp = pos + (size_t)t * Cn;
    float* xp = x + (size_t)row * Cn;
    for (int c = threadIdx.x; c < Cn; c += 256)
        xp[c] = tp[c] + pp[c];
}

// ---------------- layernorm (fp32 in, fp16 out: feeds GEMM A) ------------
__global__ void ln_kernel(const float* __restrict__ in,
                          const float* __restrict__ g,
                          const float* __restrict__ b,
                          __half* __restrict__ out) {
    int row = blockIdx.x;
    int tid = threadIdx.x;
    const float* p = in + (size_t)row * Cn;
    float s = 0.f, sq = 0.f;
    for (int c = tid; c < Cn; c += 256) { float v = p[c]; s += v; sq += v * v; }
    __shared__ float rs[256], rq[256];
    rs[tid] = s; rq[tid] = sq; __syncthreads();
    for (int o = 128; o > 0; o >>= 1) {
        if (tid < o) { rs[tid] += rs[tid + o]; rq[tid] += rq[tid + o]; }
        __syncthreads();
    }
    float mean = rs[0] * (1.f / Cn);
    float var  = rq[0] * (1.f / Cn) - mean * mean;
    float inv  = rsqrtf(var + 1e-5f);
    __half* op = out + (size_t)row * Cn;
    for (int c = tid; c < Cn; c += 256)
        op[c] = __float2half((p[c] - mean) * inv * g[c] + b[c]);
}

// ---------------- fp16 mma GEMM: C[M,N] = A[M,K] @ B[K,N] ----------------
#define APADh 40
#define BPADh 136
#define ASZh  (128 * APADh)
#define BSZh  (32 * BPADh)
#define STAGEH (ASZh + BSZh)
#define GEMM_SMEM (4 * STAGEH * 2)      // 75776 bytes

template<bool RELU, bool OUTH, bool ATOMIC>
__global__ __launch_bounds__(256, 2)
void gemm_h(const __half* __restrict__ A, const __half* __restrict__ B,
            const float* __restrict__ bias, const float* __restrict__ res,
            void* __restrict__ Cout, int N, int K) {
    extern __shared__ __half smh[];
    const int tid = threadIdx.x;
    const int lane = tid & 31, wid = tid >> 5;
    const int warp_m = (wid & 1) << 6;
    const int warp_n = (wid >> 1) << 5;
    const int m0 = blockIdx.y * 128;
    const int n0 = blockIdx.x * 128;
    const int Ksub = K / gridDim.z;
    const int koff = blockIdx.z * Ksub;

    const __half* aptr[2]; const __half* bptr[2];
    int saoff[2], sboff[2];
    #pragma unroll
    for (int j = 0; j < 2; j++) {
        int ia = j * 256 + tid;
        int ar = ia >> 2, ac = (ia & 3) << 3;
        aptr[j] = A + (size_t)(m0 + ar) * K + koff + ac;
        saoff[j] = ar * APADh + ac;
        int bk = ia >> 4, bc = (ia & 15) << 3;
        bptr[j] = B + (size_t)(koff + bk) * N + n0 + bc;
        sboff[j] = bk * BPADh + bc;
    }

    const int nk = Ksub >> 5;

    #pragma unroll
    for (int s = 0; s < 3; s++) {
        __half* As = smh + s * STAGEH;
        __half* Bs = As + ASZh;
        const int kk = s << 5;
        #pragma unroll
        for (int j = 0; j < 2; j++) {
            cp16(As + saoff[j], aptr[j] + kk);
            cp16(Bs + sboff[j], bptr[j] + (size_t)kk * N);
        }
        CP_COMMIT();
    }

    float acc[4][4][4];
    #pragma unroll
    for (int mi = 0; mi < 4; mi++)
        #pragma unroll
        for (int ni = 0; ni < 4; ni++)
            #pragma unroll
            for (int r = 0; r < 4; r++) acc[mi][ni][r] = 0.f;

    const int a_i = lane >> 3, a_r = lane & 7;
    const int arow_lane = ((a_i & 1) << 3) + a_r;
    const int acol_lane = (a_i >> 1) << 3;
    const int b_k = lane & 15;

    for (int it = 0; it < nk; ++it) {
        CP_WAIT2();
        __syncthreads();

        const __half* Ac = smh + (it & 3) * STAGEH;
        const __half* Bc = Ac + ASZh;
        #pragma unroll
        for (int ks = 0; ks < 2; ks++) {
            const int kb = ks << 4;
            uint32_t af[4][4], bf[4][2];
            #pragma unroll
            for (int mi = 0; mi < 4; mi++) {
                int row = warp_m + mi * 16 + arow_lane;
                uint32_t ad = smem_u32(Ac + row * APADh + kb + acol_lane);
                asm volatile("ldmatrix.sync.aligned.m8n8.x4.shared.b16 "
                             "{%0,%1,%2,%3}, [%4];"
                             : "=r"(af[mi][0]), "=r"(af[mi][1]),
                               "=r"(af[mi][2]), "=r"(af[mi][3]) : "r"(ad));
            }
            #pragma unroll
            for (int ni = 0; ni < 4; ni++) {
                int colB = warp_n + ni * 8;
                uint32_t bd = smem_u32(Bc + (kb + b_k) * BPADh + colB);
                asm volatile("ldmatrix.sync.aligned.m8n8.x2.trans.shared.b16 "
                             "{%0,%1}, [%2];"
                             : "=r"(bf[ni][0]), "=r"(bf[ni][1]) : "r"(bd));
            }
            #pragma unroll
            for (int mi = 0; mi < 4; mi++)
                #pragma unroll
                for (int ni = 0; ni < 4; ni++)
                    MMA_F16(acc[mi][ni], af[mi], bf[ni][0], bf[ni][1]);
        }

        if (it + 3 < nk) {
            const int kk = (it + 3) << 5;
            __half* As = smh + ((it + 3) & 3) * STAGEH;
            __half* Bs = As + ASZh;
            #pragma unroll
            for (int j = 0; j < 2; j++) {
                cp16(As + saoff[j], aptr[j] + kk);
                cp16(Bs + sboff[j], bptr[j] + (size_t)kk * N);
            }
        }
        CP_COMMIT();
    }

    const bool addb = (bias != nullptr) && (!ATOMIC || blockIdx.z == 0);
    #pragma unroll
    for (int mi = 0; mi < 4; mi++) {
        int row = m0 + warp_m + mi * 16 + (lane >> 2);
        #pragma unroll
        for (int ni = 0; ni < 4; ni++) {
            int col = n0 + warp_n + ni * 8 + ((lane & 3) << 1);
            float v0 = acc[mi][ni][0], v1 = acc[mi][ni][1];
            float v2 = acc[mi][ni][2], v3 = acc[mi][ni][3];
            if (addb) {
                float b0 = bias[col], b1 = bias[col + 1];
                v0 += b0; v1 += b1; v2 += b0; v3 += b1;
            }
            if (RELU) {
                v0 = fmaxf(v0, 0.f); v1 = fmaxf(v1, 0.f);
                v2 = fmaxf(v2, 0.f); v3 = fmaxf(v3, 0.f);
            }
            if (ATOMIC) {
                float* Cp = (float*)Cout;
                atomicAdd(Cp + (size_t)row * N + col,       v0);
                atomicAdd(Cp + (size_t)row * N + col + 1,   v1);
                atomicAdd(Cp + (size_t)(row + 8) * N + col,     v2);
                atomicAdd(Cp + (size_t)(row + 8) * N + col + 1, v3);
            } else if (OUTH) {
                __half* Cp = (__half*)Cout;
                *(__half2*)(Cp + (size_t)row * N + col) = __floats2half2_rn(v0, v1);
                *(__half2*)(Cp + (size_t)(row + 8) * N + col) = __floats2half2_rn(v2, v3);
            } else {
                float* Cp = (float*)Cout;
                if (res) {
                    const float2 r0 = *(const float2*)(res + (size_t)row * N + col);
                    const float2 r1 = *(const float2*)(res + (size_t)(row + 8) * N + col);
                    v0 += r0.x; v1 += r0.y; v2 += r1.x; v3 += r1.y;
                }
                *(float2*)(Cp + (size_t)row * N + col) = make_float2(v0, v1);
                *(float2*)(Cp + (size_t)(row + 8) * N + col) = make_float2(v2, v3);
            }
        }
    }
}

// ---------------- tensor-core flash attention -----------------------------
// Block = 64 t-rows of one (b,h); 4 warps x 16 rows. S and PV on fp16 mma.
#define QP 72    // smem pitch (halves); 144B -> ldmatrix conflict-free

__global__ __launch_bounds__(128)
void attn_mma(const __half* __restrict__ qkv, __half* __restrict__ y) {
    const int tt = blockIdx.x, h = blockIdx.y, b = blockIdx.z;
    const int tid = threadIdx.x, lane = tid & 31, wid = tid >> 5;
    __shared__ __align__(16) __half sQ[64 * QP];
    __shared__ __align__(16) __half sK[64 * QP];
    __shared__ __align__(16) __half sV[64 * QP];
    const size_t base = (size_t)b * Tn * C3 + (size_t)h * HDn;
    const int t0 = tt * 64;

    // stage Q tile (64 rows x 64 halves)
    for (int i = tid; i < 512; i += 128) {
        int row = i >> 3, c8 = (i & 7) << 3;
        *(uint4*)(sQ + row * QP + c8) =
            *(const uint4*)(qkv + base + (size_t)(t0 + row) * C3 + c8);
    }
    __syncthreads();

    // preload Q A-fragments (rows wid*16..+15, 4 k-steps)
    const int a_i = lane >> 3;
    const int arow = ((a_i & 1) << 3) + (lane & 7);
    const int acol = (a_i >> 1) << 3;
    uint32_t qA[4][4];
    #pragma unroll
    for (int kt = 0; kt < 4; kt++) {
        uint32_t ad = smem_u32(sQ + (wid * 16 + arow) * QP + kt * 16 + acol);
        asm volatile("ldmatrix.sync.aligned.m8n8.x4.shared.b16 "
                     "{%0,%1,%2,%3}, [%4];"
                     : "=r"(qA[kt][0]), "=r"(qA[kt][1]),
                       "=r"(qA[kt][2]), "=r"(qA[kt][3]) : "r"(ad));
    }

    float o[8][4];
    #pragma unroll
    for (int ni = 0; ni < 8; ni++)
        #pragma unroll
        for (int r = 0; r < 4; r++) o[ni][r] = 0.f;
    float m0 = -1e30f, m1 = -1e30f, l0 = 0.f, l1 = 0.f;

    const int c_lane = (lane & 3) << 1;
    const int tr0 = t0 + wid * 16 + (lane >> 2);   // global row (r); r+8 = tr0+8

    // K B-frag addressing (non-trans x4): n-row + k-col per lane
    const int kb_n = (lane & 7) + ((lane >> 4) & 1) * 8;
    const int kb_k = ((lane >> 3) & 1) * 8;
    // V B-frag addressing (trans x4): k-row + n-col per lane
    const int vb_k = (lane & 7) + ((lane >> 3) & 1) * 8;
    const int vb_n = ((lane >> 4) & 1) * 8;

    for (int st = 0; st <= tt; ++st) {
        const int s0 = st * 64;
        for (int i = tid; i < 512; i += 128) {
            int row = i >> 3, c8 = (i & 7) << 3;
            size_t g = base + (size_t)(s0 + row) * C3 + c8;
            *(uint4*)(sK + row * QP + c8) = *(const uint4*)(qkv + g + Cn);
            *(uint4*)(sV + row * QP + c8) = *(const uint4*)(qkv + g + 2 * Cn);
        }
        __syncthreads();

        // ---- S = Q @ K^T  (fp32 accum in s[8][4]) ----
        float s[8][4];
        #pragma unroll
        for (int ni = 0; ni < 8; ni++)
            #pragma unroll
            for (int r = 0; r < 4; r++) s[ni][r] = 0.f;

        #pragma unroll
        for (int kt = 0; kt < 4; kt++) {
            #pragma unroll
            for (int nj = 0; nj < 4; nj++) {
                uint32_t bf[4];
                uint32_t bd = smem_u32(sK + (nj * 16 + kb_n) * QP + kt * 16 + kb_k);
                asm volatile("ldmatrix.sync.aligned.m8n8.x4.shared.b16 "
                             "{%0,%1,%2,%3}, [%4];"
                             : "=r"(bf[0]), "=r"(bf[1]), "=r"(bf[2]), "=r"(bf[3])
                             : "r"(bd));
                MMA_F16(s[nj * 2],     qA[kt], bf[0], bf[1]);
                MMA_F16(s[nj * 2 + 1], qA[kt], bf[2], bf[3]);
            }
        }

        // ---- scale + causal mask ----
        #pragma unroll
        for (int ni = 0; ni < 8; ni++) {
            s[ni][0] *= 0.125f; s[ni][1] *= 0.125f;
            s[ni][2] *= 0.125f; s[ni][3] *= 0.125f;
        }
        if (st == tt) {
            #pragma unroll
            for (int ni = 0; ni < 8; ni++) {
                int sc = s0 + ni * 8 + c_lane;
                if (sc     > tr0)     s[ni][0] = -1e30f;
                if (sc + 1 > tr0)     s[ni][1] = -1e30f;
                if (sc     > tr0 + 8) s[ni][2] = -1e30f;
                if (sc + 1 > tr0 + 8) s[ni][3] = -1e30f;
            }
        }

        // ---- online softmax (rows r and r+8) ----
        float tm0 = m0, tm1 = m1;
        #pragma unroll
        for (int ni = 0; ni < 8; ni++) {
            tm0 = fmaxf(tm0, fmaxf(s[ni][0], s[ni][1]));
            tm1 = fmaxf(tm1, fmaxf(s[ni][2], s[ni][3]));
        }
        tm0 = fmaxf(tm0, __shfl_xor_sync(0xffffffffu, tm0, 1));
        tm0 = fmaxf(tm0, __shfl_xor_sync(0xffffffffu, tm0, 2));
        tm1 = fmaxf(tm1, __shfl_xor_sync(0xffffffffu, tm1, 1));
        tm1 = fmaxf(tm1, __shfl_xor_sync(0xffffffffu, tm1, 2));
        if (tm0 > m0) {
            float sc_ = __expf(m0 - tm0);
            l0 *= sc_;
            #pragma unroll
            for (int ni = 0; ni < 8; ni++) { o[ni][0] *= sc_; o[ni][1] *= sc_; }
            m0 = tm0;
        }
        if (tm1 > m1) {
            float sc_ = __expf(m1 - tm1);
            l1 *= sc_;
            #pragma unroll
            for (int ni = 0; ni < 8; ni++) { o[ni][2] *= sc_; o[ni][3] *= sc_; }
            m1 = tm1;
        }
        #pragma unroll
        for (int ni = 0; ni < 8; ni++) {
            s[ni][0] = __expf(s[ni][0] - m0);
            s[ni][1] = __expf(s[ni][1] - m0);
            s[ni][2] = __expf(s[ni][2] - m1);
            s[ni][3] = __expf(s[ni][3] - m1);
            l0 += s[ni][0] + s[ni][1];
            l1 += s[ni][2] + s[ni][3];
        }

        // ---- P (C-frag) -> A-frags for PV ----
        uint32_t aP[4][4];
        #pragma unroll
        for (int kt = 0; kt < 4; kt++) {
            __half2 h0 = __floats2half2_rn(s[2 * kt][0],     s[2 * kt][1]);
            __half2 h1 = __floats2half2_rn(s[2 * kt][2],     s[2 * kt][3]);
            __half2 h2v = __floats2half2_rn(s[2 * kt + 1][0], s[2 * kt + 1][1]);
            __half2 h3 = __floats2half2_rn(s[2 * kt + 1][2], s[2 * kt + 1][3]);
            aP[kt][0] = *(uint32_t*)&h0;
            aP[kt][1] = *(uint32_t*)&h1;
            aP[kt][2] = *(uint32_t*)&h2v;
            aP[kt][3] = *(uint32_t*)&h3;
        }

        // ---- O += P @ V ----
        #pragma unroll
        for (int kt = 0; kt < 4; kt++) {
            #pragma unroll
            for (int nj = 0; nj < 4; nj++) {
                uint32_t bv[4];
                uint32_t bd = smem_u32(sV + (kt * 16 + vb_k) * QP + nj * 16 + vb_n);
                asm volatile("ldmatrix.sync.aligned.m8n8.x4.trans.shared.b16 "
                             "{%0,%1,%2,%3}, [%4];"
                             : "=r"(bv[0]), "=r"(bv[1]), "=r"(bv[2]), "=r"(bv[3])
                             : "r"(bd));
                MMA_F16(o[nj * 2],     aP[kt], bv[0], bv[1]);
                MMA_F16(o[nj * 2 + 1], aP[kt], bv[2], bv[3]);
            }
        }
        __syncthreads();
    }

    // ---- finalize: quad-sum l, normalize, store fp16 ----
    l0 += __shfl_xor_sync(0xffffffffu, l0, 1);
    l0 += __shfl_xor_sync(0xffffffffu, l0, 2);
    l1 += __shfl_xor_sync(0xffffffffu, l1, 1);
    l1 += __shfl_xor_sync(0xffffffffu, l1, 2);
    const float inv0 = 1.f / l0, inv1 = 1.f / l1;
    const size_t ybase = (size_t)b * Tn * Cn + (size_t)h * HDn;
    #pragma unroll
    for (int ni = 0; ni < 8; ni++) {
        int d = ni * 8 + c_lane;
        *(__half2*)(y + ybase + (size_t)tr0 * Cn + d) =
            __floats2half2_rn(o[ni][0] * inv0, o[ni][1] * inv0);
        *(__half2*)(y + ybase + (size_t)(tr0 + 8) * Cn + d) =
            __floats2half2_rn(o[ni][2] * inv1, o[ni][3] * inv1);
    }
}

// ---------------- launch ----------------
extern "C" void kernel_launch(void* const* d_in, const int* in_sizes, int n_in,
                              void* d_out, int out_size) {
    const int*   idx   = (const int*)  d_in[0];
    const float* tok   = (const float*)d_in[1];
    const float* pos   = (const float*)d_in[2];
    const float* wq    = (const float*)d_in[3];
    const float* wk    = (const float*)d_in[4];
    const float* wv    = (const float*)d_in[5];
    const float* wo    = (const float*)d_in[6];
    const float* bo    = (const float*)d_in[7];
    const float* ln1g  = (const float*)d_in[8];
    const float* ln1b  = (const float*)d_in[9];
    const float* ln2g  = (const float*)d_in[10];
    const float* ln2b  = (const float*)d_in[11];
    const float* w1    = (const float*)d_in[12];
    const float* b1    = (const float*)d_in[13];
    const float* w2    = (const float*)d_in[14];
    const float* b2    = (const float*)d_in[15];
    const float* lnfg  = (const float*)d_in[16];
    const float* lnfb  = (const float*)d_in[17];
    const float* wlm   = (const float*)d_in[18];
    float* out = (float*)d_out;

    float *x;
    __half *xn, *qkv, *y, *h;
    __half *wqkvH, *woH, *w1H, *w2H, *wlmH;
    cudaGetSymbolAddress((void**)&x,   g_x);
    cudaGetSymbolAddress((void**)&xn,  g_xn);
    cudaGetSymbolAddress((void**)&qkv, g_qkv);
    cudaGetSymbolAddress((void**)&y,   g_y);
    cudaGetSymbolAddress((void**)&h,   g_h);
    cudaGetSymbolAddress((void**)&wqkvH, g_wqkvH);
    cudaGetSymbolAddress((void**)&woH, g_woH);
    cudaGetSymbolAddress((void**)&w1H, g_w1H);
    cudaGetSymbolAddress((void**)&w2H, g_w2H);
    cudaGetSymbolAddress((void**)&wlmH, g_wlmH);

    cudaFuncSetAttribute(gemm_h<false, true, false>,
                         cudaFuncAttributeMaxDynamicSharedMemorySize, GEMM_SMEM);
    cudaFuncSetAttribute(gemm_h<true, true, false>,
                         cudaFuncAttributeMaxDynamicSharedMemorySize, GEMM_SMEM);
    cudaFuncSetAttribute(gemm_h<false, false, false>,
                         cudaFuncAttributeMaxDynamicSharedMemorySize, GEMM_SMEM);
    cudaFuncSetAttribute(gemm_h<false, false, true>,
                         cudaFuncAttributeMaxDynamicSharedMemorySize, GEMM_SMEM);

    round_weights<<<dim3(N_FF / 8 / 256, 7), 256>>>(
        wq, wk, wv, wo, w1, w2, wlm, wqkvH, woH, w1H, w2H, wlmH);
    embed_kernel<<<BT, 256>>>(idx, tok, pos, x);

    const dim3 gQKV(C3 / 128, BT / 128);       // 384
    const dim3 gCCs(Cn / 128, BT / 128, 2);    // 256 (split-K)
    const dim3 gCF(Fn / 128, BT / 128);        // 512
    const dim3 gCV(Vn / 128, BT / 128);        // 4000
    const dim3 gAttn(Tn / 64, Hn, Bn);         // 8 x 16 x 4

    for (int l = 0; l < Ln; l++) {
        const __half* wqkvl = wqkvH + (size_t)l * Cn * C3;
        const __half* woHl = woH + (size_t)l * Cn * Cn;
        const float* bol  = bo + (size_t)l * Cn;
        const __half* w1Hl = w1H + (size_t)l * Cn * Fn;
        const float* b1l  = b1 + (size_t)l * Fn;
        const __half* w2Hl = w2H + (size_t)l * Fn * Cn;
        const float* b2l  = b2 + (size_t)l * Cn;

        ln_kernel<<<BT, 256>>>(x, ln1g + l * Cn, ln1b + l * Cn, xn);
        gemm_h<false, true, false><<<gQKV, 256, GEMM_SMEM>>>(xn, wqkvl, nullptr, nullptr, qkv, C3, Cn);
        attn_mma<<<gAttn, 128>>>(qkv, y);
        gemm_h<false, false, true><<<gCCs, 256, GEMM_SMEM>>>(y, woHl, bol, nullptr, x, Cn, Cn);

        ln_kernel<<<BT, 256>>>(x, ln2g + l * Cn, ln2b + l * Cn, xn);
        gemm_h<true, true, false><<<gCF, 256, GEMM_SMEM>>>(xn, w1Hl, b1l, nullptr, h, Fn, Cn);
        gemm_h<false, false, true><<<gCCs, 256, GEMM_SMEM>>>(h, w2Hl, b2l, nullptr, x, Cn, Fn);
    }

    ln_kernel<<<BT, 256>>>(x, lnfg, lnfb, xn);
    gemm_h<false, false, false><<<gCV, 256, GEMM_SMEM>>>(xn, wlmH, nullptr, nullptr, out, Vn, Cn);
}

// round 10
// speedup vs baseline: 2.8772x; 1.0530x over previous
#include <cuda_runtime.h>
#include <cuda_fp16.h>
#include <cstdint>
#include <math.h>

// GPT forward: B=4, T=512, L=12, C=1024, H=16, HD=64, F=4096, V=32000
#define Bn   4
#define Tn   512
#define Ln   12
#define Cn   1024
#define Hn   16
#define HDn  64
#define Fn   4096
#define Vn   32000
#define BT   (Bn * Tn)          // 2048
#define C3   (3 * Cn)           // 3072

// ---------------- static scratch (no allocations allowed) ----------------
__device__ float  g_x  [BT * Cn];            // residual stream (fp32)
__device__ __half g_xn [BT * Cn];
__device__ __half g_qkv[BT * C3];
__device__ __half g_y  [BT * Cn];
__device__ __half g_h  [BT * Fn];
// fp16 weights; wq/wk/wv packed into [C, 3C] per layer
__device__ __half g_wqkvH[(size_t)Ln * Cn * C3];
__device__ __half g_woH[Ln * Cn * Cn];
__device__ __half g_w1H[Ln * Cn * Fn];
__device__ __half g_w2H[Ln * Fn * Cn];
__device__ __half g_wlmH[(size_t)Vn * Cn];

__device__ __forceinline__ uint32_t smem_u32(const void* p) {
    uint32_t a;
    asm("{ .reg .u64 t; cvta.to.shared.u64 t, %1; cvt.u32.u64 %0, t; }"
        : "=r"(a) : "l"(p));
    return a;
}
__device__ __forceinline__ void cp16(void* s, const void* g) {
    asm volatile("cp.async.cg.shared.global [%0], [%1], 16;"
                 :: "r"(smem_u32(s)), "l"(g) : "memory");
}
#define CP_COMMIT() asm volatile("cp.async.commit_group;" ::: "memory")
#define CP_WAIT2()  asm volatile("cp.async.wait_group 2;" ::: "memory")

#define MMA_F16(acc, a, b0, b1) \
    asm volatile( \
        "mma.sync.aligned.m16n8k16.row.col.f32.f16.f16.f32 " \
        "{%0,%1,%2,%3}, {%4,%5,%6,%7}, {%8,%9}, {%0,%1,%2,%3};" \
        : "+f"((acc)[0]), "+f"((acc)[1]), "+f"((acc)[2]), "+f"((acc)[3]) \
        : "r"((a)[0]), "r"((a)[1]), "r"((a)[2]), "r"((a)[3]), \
          "r"(b0), "r"(b1))

// ---------------- one-shot weight rounding / packing to fp16 -------------
#define N_QKVO (Ln * Cn * Cn)          // 12,582,912
#define N_FF   (Ln * Cn * Fn)          // 50,331,648
#define N_LM   ((size_t)Vn * Cn)       // 32,768,000

__global__ void round_weights(const float* wq, const float* wk, const float* wv,
                              const float* wo, const float* w1, const float* w2,
                              const float* wlm,
                              __half* wqkvH, __half* woH,
                              __half* w1H, __half* w2H, __half* wlmH) {
    const float* in; __half* out; size_t n;
    int sel = -1;
    switch (blockIdx.y) {
        case 0: in = wq;  out = wqkvH; n = N_QKVO; sel = 0; break;
        case 1: in = wk;  out = wqkvH; n = N_QKVO; sel = 1; break;
        case 2: in = wv;  out = wqkvH; n = N_QKVO; sel = 2; break;
        case 3: in = wo;  out = woH;  n = N_QKVO; break;
        case 4: in = w1;  out = w1H;  n = N_FF;   break;
        case 5: in = w2;  out = w2H;  n = N_FF;   break;
        default: in = wlm; out = wlmH; n = N_LM;  break;
    }
    size_t i = ((size_t)blockIdx.x * 256 + threadIdx.x) * 8;
    if (i >= n) return;
    float4 v0 = *(const float4*)(in + i);
    float4 v1 = *(const float4*)(in + i + 4);
    __half2 h[4];
    h[0] = __floats2half2_rn(v0.x, v0.y);
    h[1] = __floats2half2_rn(v0.z, v0.w);
    h[2] = __floats2half2_rn(v1.x, v1.y);
    h[3] = __floats2half2_rn(v1.z, v1.w);
    size_t oi = i;
    if (sel >= 0) {
        size_t l = i / (Cn * Cn);
        size_t rem = i - l * Cn * Cn;
        size_t kk = rem / Cn, nn = rem % Cn;
        oi = (l * Cn + kk) * C3 + (size_t)sel * Cn + nn;
    }
    *(uint4*)(out + oi) = *(uint4*)h;
}

// ---------------- embedding (x stays fp32: residual stream) --------------
__global__ void embed_kernel(const int* __restrict__ idx,
                             const float* __restrict__ tok,
                             const float* __restrict__ pos,
                             float* __restrict__ x) {
    int row = blockIdx.x;
    int t = row & (Tn - 1);
    int token = idx[row];
    const float* tp = tok + (size_t)token * Cn;
    const float* pp = pos + (size_t)t * Cn;
    float* xp = x + (size_t)row * Cn;
    for (int c = threadIdx.x; c < Cn; c += 256)
        xp[c] = tp[c] + pp[c];
}

// ---------------- layernorm (fp32 in, fp16 out: feeds GEMM A) ------------
__global__ void ln_kernel(const float* __restrict__ in,
                          const float* __restrict__ g,
                          const float* __restrict__ b,
                          __half* __restrict__ out) {
    int row = blockIdx.x;
    int tid = threadIdx.x;
    const float* p = in + (size_t)row * Cn;
    float s = 0.f, sq = 0.f;
    for (int c = tid; c < Cn; c += 256) { float v = p[c]; s += v; sq += v * v; }
    __shared__ float rs[256], rq[256];
    rs[tid] = s; rq[tid] = sq; __syncthreads();
    for (int o = 128; o > 0; o >>= 1) {
        if (tid < o) { rs[tid] += rs[tid + o]; rq[tid] += rq[tid + o]; }
        __syncthreads();
    }
    float mean = rs[0] * (1.f / Cn);
    float var  = rq[0] * (1.f / Cn) - mean * mean;
    float inv  = rsqrtf(var + 1e-5f);
    __half* op = out + (size_t)row * Cn;
    for (int c = tid; c < Cn; c += 256)
        op[c] = __float2half((p[c] - mean) * inv * g[c] + b[c]);
}

// ---------------- fp16 mma GEMM: C[M,N] = A[M,K] @ B[K,N] ----------------
// CTA 128x128, 4 warps (128 thr), warp tile 64x64 (MI=4 x NI=8).
// BK=32, 4-stage cp.async, one __syncthreads per chunk, 2 CTAs/SM.
#define APADh 40
#define BPADh 136
#define ASZh  (128 * APADh)
#define BSZh  (32 * BPADh)
#define STAGEH (ASZh + BSZh)
#define GEMM_SMEM (4 * STAGEH * 2)      // 75776 bytes

template<bool RELU, bool OUTH, bool ATOMIC>
__global__ __launch_bounds__(128, 2)
void gemm_h(const __half* __restrict__ A, const __half* __restrict__ B,
            const float* __restrict__ bias, const float* __restrict__ res,
            void* __restrict__ Cout, int N, int K) {
    extern __shared__ __half smh[];
    const int tid = threadIdx.x;
    const int lane = tid & 31, wid = tid >> 5;
    const int warp_m = (wid & 1) << 6;     // 0 or 64
    const int warp_n = (wid >> 1) << 6;    // 0 or 64
    const int m0 = blockIdx.y * 128;
    const int n0 = blockIdx.x * 128;
    const int Ksub = K / gridDim.z;
    const int koff = blockIdx.z * Ksub;

    // load slots: A tile 128x32 halves (4 x16B per thread), B 32x128 (4)
    const __half* aptr[4]; const __half* bptr[4];
    int saoff[4], sboff[4];
    #pragma unroll
    for (int j = 0; j < 4; j++) {
        int ia = j * 128 + tid;                    // 0..511
        int ar = ia >> 2, ac = (ia & 3) << 3;      // row 0..127, k 0,8,16,24
        aptr[j] = A + (size_t)(m0 + ar) * K + koff + ac;
        saoff[j] = ar * APADh + ac;
        int bk = ia >> 4, bc = (ia & 15) << 3;     // k 0..31, n 0,8..120
        bptr[j] = B + (size_t)(koff + bk) * N + n0 + bc;
        sboff[j] = bk * BPADh + bc;
    }

    const int nk = Ksub >> 5;

    #pragma unroll
    for (int s = 0; s < 3; s++) {
        __half* As = smh + s * STAGEH;
        __half* Bs = As + ASZh;
        const int kk = s << 5;
        #pragma unroll
        for (int j = 0; j < 4; j++) {
            cp16(As + saoff[j], aptr[j] + kk);
            cp16(Bs + sboff[j], bptr[j] + (size_t)kk * N);
        }
        CP_COMMIT();
    }

    float acc[4][8][4];
    #pragma unroll
    for (int mi = 0; mi < 4; mi++)
        #pragma unroll
        for (int ni = 0; ni < 8; ni++)
            #pragma unroll
            for (int r = 0; r < 4; r++) acc[mi][ni][r] = 0.f;

    // A-fragment lane addressing (non-trans x4)
    const int a_i = lane >> 3;
    const int arow_lane = ((a_i & 1) << 3) + (lane & 7);
    const int acol_lane = (a_i >> 1) << 3;
    // B-fragment lane addressing (trans x4): k-row + n-col
    const int vb_k = (lane & 7) + ((lane >> 3) & 1) * 8;
    const int vb_n = ((lane >> 4) & 1) * 8;

    for (int it = 0; it < nk; ++it) {
        CP_WAIT2();
        __syncthreads();

        const __half* Ac = smh + (it & 3) * STAGEH;
        const __half* Bc = Ac + ASZh;
        #pragma unroll
        for (int ks = 0; ks < 2; ks++) {
            const int kb = ks << 4;
            uint32_t af[4][4];
            #pragma unroll
            for (int mi = 0; mi < 4; mi++) {
                int row = warp_m + mi * 16 + arow_lane;
                uint32_t ad = smem_u32(Ac + row * APADh + kb + acol_lane);
                asm volatile("ldmatrix.sync.aligned.m8n8.x4.shared.b16 "
                             "{%0,%1,%2,%3}, [%4];"
                             : "=r"(af[mi][0]), "=r"(af[mi][1]),
                               "=r"(af[mi][2]), "=r"(af[mi][3]) : "r"(ad));
            }
            #pragma unroll
            for (int nj = 0; nj < 4; nj++) {
                uint32_t bv[4];
                uint32_t bd = smem_u32(Bc + (kb + vb_k) * BPADh
                                       + warp_n + nj * 16 + vb_n);
                asm volatile("ldmatrix.sync.aligned.m8n8.x4.trans.shared.b16 "
                             "{%0,%1,%2,%3}, [%4];"
                             : "=r"(bv[0]), "=r"(bv[1]), "=r"(bv[2]), "=r"(bv[3])
                             : "r"(bd));
                #pragma unroll
                for (int mi = 0; mi < 4; mi++) {
                    MMA_F16(acc[mi][nj * 2],     af[mi], bv[0], bv[1]);
                    MMA_F16(acc[mi][nj * 2 + 1], af[mi], bv[2], bv[3]);
                }
            }
        }

        if (it + 3 < nk) {
            const int kk = (it + 3) << 5;
            __half* As = smh + ((it + 3) & 3) * STAGEH;
            __half* Bs = As + ASZh;
            #pragma unroll
            for (int j = 0; j < 4; j++) {
                cp16(As + saoff[j], aptr[j] + kk);
                cp16(Bs + sboff[j], bptr[j] + (size_t)kk * N);
            }
        }
        CP_COMMIT();
    }

    const bool addb = (bias != nullptr) && (!ATOMIC || blockIdx.z == 0);
    #pragma unroll
    for (int mi = 0; mi < 4; mi++) {
        int row = m0 + warp_m + mi * 16 + (lane >> 2);
        #pragma unroll
        for (int ni = 0; ni < 8; ni++) {
            int col = n0 + warp_n + ni * 8 + ((lane & 3) << 1);
            float v0 = acc[mi][ni][0], v1 = acc[mi][ni][1];
            float v2 = acc[mi][ni][2], v3 = acc[mi][ni][3];
            if (addb) {
                float b0 = bias[col], b1 = bias[col + 1];
                v0 += b0; v1 += b1; v2 += b0; v3 += b1;
            }
            if (RELU) {
                v0 = fmaxf(v0, 0.f); v1 = fmaxf(v1, 0.f);
                v2 = fmaxf(v2, 0.f); v3 = fmaxf(v3, 0.f);
            }
            if (ATOMIC) {
                float* Cp = (float*)Cout;
                atomicAdd(Cp + (size_t)row * N + col,       v0);
                atomicAdd(Cp + (size_t)row * N + col + 1,   v1);
                atomicAdd(Cp + (size_t)(row + 8) * N + col,     v2);
                atomicAdd(Cp + (size_t)(row + 8) * N + col + 1, v3);
            } else if (OUTH) {
                __half* Cp = (__half*)Cout;
                *(__half2*)(Cp + (size_t)row * N + col) = __floats2half2_rn(v0, v1);
                *(__half2*)(Cp + (size_t)(row + 8) * N + col) = __floats2half2_rn(v2, v3);
            } else {
                float* Cp = (float*)Cout;
                if (res) {
                    const float2 r0 = *(const float2*)(res + (size_t)row * N + col);
                    const float2 r1 = *(const float2*)(res + (size_t)(row + 8) * N + col);
                    v0 += r0.x; v1 += r0.y; v2 += r1.x; v3 += r1.y;
                }
                *(float2*)(Cp + (size_t)row * N + col) = make_float2(v0, v1);
                *(float2*)(Cp + (size_t)(row + 8) * N + col) = make_float2(v2, v3);
            }
        }
    }
}

// ---------------- tensor-core flash attention -----------------------------
#define QP 72

__global__ __launch_bounds__(128)
void attn_mma(const __half* __restrict__ qkv, __half* __restrict__ y) {
    const int tt = blockIdx.x, h = blockIdx.y, b = blockIdx.z;
    const int tid = threadIdx.x, lane = tid & 31, wid = tid >> 5;
    __shared__ __align__(16) __half sQ[64 * QP];
    __shared__ __align__(16) __half sK[64 * QP];
    __shared__ __align__(16) __half sV[64 * QP];
    const size_t base = (size_t)b * Tn * C3 + (size_t)h * HDn;
    const int t0 = tt * 64;

    for (int i = tid; i < 512; i += 128) {
        int row = i >> 3, c8 = (i & 7) << 3;
        *(uint4*)(sQ + row * QP + c8) =
            *(const uint4*)(qkv + base + (size_t)(t0 + row) * C3 + c8);
    }
    __syncthreads();

    const int a_i = lane >> 3;
    const int arow = ((a_i & 1) << 3) + (lane & 7);
    const int acol = (a_i >> 1) << 3;
    uint32_t qA[4][4];
    #pragma unroll
    for (int kt = 0; kt < 4; kt++) {
        uint32_t ad = smem_u32(sQ + (wid * 16 + arow) * QP + kt * 16 + acol);
        asm volatile("ldmatrix.sync.aligned.m8n8.x4.shared.b16 "
                     "{%0,%1,%2,%3}, [%4];"
                     : "=r"(qA[kt][0]), "=r"(qA[kt][1]),
                       "=r"(qA[kt][2]), "=r"(qA[kt][3]) : "r"(ad));
    }

    float o[8][4];
    #pragma unroll
    for (int ni = 0; ni < 8; ni++)
        #pragma unroll
        for (int r = 0; r < 4; r++) o[ni][r] = 0.f;
    float m0 = -1e30f, m1 = -1e30f, l0 = 0.f, l1 = 0.f;

    const int c_lane = (lane & 3) << 1;
    const int tr0 = t0 + wid * 16 + (lane >> 2);

    const int kb_n = (lane & 7) + ((lane >> 4) & 1) * 8;
    const int kb_k = ((lane >> 3) & 1) * 8;
    const int vb_k = (lane & 7) + ((lane >> 3) & 1) * 8;
    const int vb_n = ((lane >> 4) & 1) * 8;

    for (int st = 0; st <= tt; ++st) {
        const int s0 = st * 64;
        for (int i = tid; i < 512; i += 128) {
            int row = i >> 3, c8 = (i & 7) << 3;
            size_t g = base + (size_t)(s0 + row) * C3 + c8;
            *(uint4*)(sK + row * QP + c8) = *(const uint4*)(qkv + g + Cn);
            *(uint4*)(sV + row * QP + c8) = *(const uint4*)(qkv + g + 2 * Cn);
        }
        __syncthreads();

        float s[8][4];
        #pragma unroll
        for (int ni = 0; ni < 8; ni++)
            #pragma unroll
            for (int r = 0; r < 4; r++) s[ni][r] = 0.f;

        #pragma unroll
        for (int kt = 0; kt < 4; kt++) {
            #pragma unroll
            for (int nj = 0; nj < 4; nj++) {
                uint32_t bf[4];
                uint32_t bd = smem_u32(sK + (nj * 16 + kb_n) * QP + kt * 16 + kb_k);
                asm volatile("ldmatrix.sync.aligned.m8n8.x4.shared.b16 "
                             "{%0,%1,%2,%3}, [%4];"
                             : "=r"(bf[0]), "=r"(bf[1]), "=r"(bf[2]), "=r"(bf[3])
                             : "r"(bd));
                MMA_F16(s[nj * 2],     qA[kt], bf[0], bf[1]);
                MMA_F16(s[nj * 2 + 1], qA[kt], bf[2], bf[3]);
            }
        }

        #pragma unroll
        for (int ni = 0; ni < 8; ni++) {
            s[ni][0] *= 0.125f; s[ni][1] *= 0.125f;
            s[ni][2] *= 0.125f; s[ni][3] *= 0.125f;
        }
        if (st == tt) {
            #pragma unroll
            for (int ni = 0; ni < 8; ni++) {
                int sc = s0 + ni * 8 + c_lane;
                if (sc     > tr0)     s[ni][0] = -1e30f;
                if (sc + 1 > tr0)     s[ni][1] = -1e30f;
                if (sc     > tr0 + 8) s[ni][2] = -1e30f;
                if (sc + 1 > tr0 + 8) s[ni][3] = -1e30f;
            }
        }

        float tm0 = m0, tm1 = m1;
        #pragma unroll
        for (int ni = 0; ni < 8; ni++) {
            tm0 = fmaxf(tm0, fmaxf(s[ni][0], s[ni][1]));
            tm1 = fmaxf(tm1, fmaxf(s[ni][2], s[ni][3]));
        }
        tm0 = fmaxf(tm0, __shfl_xor_sync(0xffffffffu, tm0, 1));
        tm0 = fmaxf(tm0, __shfl_xor_sync(0xffffffffu, tm0, 2));
        tm1 = fmaxf(tm1, __shfl_xor_sync(0xffffffffu, tm1, 1));
        tm1 = fmaxf(tm1, __shfl_xor_sync(0xffffffffu, tm1, 2));
        if (tm0 > m0) {
            float sc_ = __expf(m0 - tm0);
            l0 *= sc_;
            #pragma unroll
            for (int ni = 0; ni < 8; ni++) { o[ni][0] *= sc_; o[ni][1] *= sc_; }
            m0 = tm0;
        }
        if (tm1 > m1) {
            float sc_ = __expf(m1 - tm1);
            l1 *= sc_;
            #pragma unroll
            for (int ni = 0; ni < 8; ni++) { o[ni][2] *= sc_; o[ni][3] *= sc_; }
            m1 = tm1;
        }
        #pragma unroll
        for (int ni = 0; ni < 8; ni++) {
            s[ni][0] = __expf(s[ni][0] - m0);
            s[ni][1] = __expf(s[ni][1] - m0);
            s[ni][2] = __expf(s[ni][2] - m1);
            s[ni][3] = __expf(s[ni][3] - m1);
            l0 += s[ni][0] + s[ni][1];
            l1 += s[ni][2] + s[ni][3];
        }

        uint32_t aP[4][4];
        #pragma unroll
        for (int kt = 0; kt < 4; kt++) {
            __half2 h0 = __floats2half2_rn(s[2 * kt][0],     s[2 * kt][1]);
            __half2 h1 = __floats2half2_rn(s[2 * kt][2],     s[2 * kt][3]);
            __half2 h2v = __floats2half2_rn(s[2 * kt + 1][0], s[2 * kt + 1][1]);
            __half2 h3 = __floats2half2_rn(s[2 * kt + 1][2], s[2 * kt + 1][3]);
            aP[kt][0] = *(uint32_t*)&h0;
            aP[kt][1] = *(uint32_t*)&h1;
            aP[kt][2] = *(uint32_t*)&h2v;
            aP[kt][3] = *(uint32_t*)&h3;
        }

        #pragma unroll
        for (int kt = 0; kt < 4; kt++) {
            #pragma unroll
            for (int nj = 0; nj < 4; nj++) {
                uint32_t bv[4];
                uint32_t bd = smem_u32(sV + (kt * 16 + vb_k) * QP + nj * 16 + vb_n);
                asm volatile("ldmatrix.sync.aligned.m8n8.x4.trans.shared.b16 "
                             "{%0,%1,%2,%3}, [%4];"
                             : "=r"(bv[0]), "=r"(bv[1]), "=r"(bv[2]), "=r"(bv[3])
                             : "r"(bd));
                MMA_F16(o[nj * 2],     aP[kt], bv[0], bv[1]);
                MMA_F16(o[nj * 2 + 1], aP[kt], bv[2], bv[3]);
            }
        }
        __syncthreads();
    }

    l0 += __shfl_xor_sync(0xffffffffu, l0, 1);
    l0 += __shfl_xor_sync(0xffffffffu, l0, 2);
    l1 += __shfl_xor_sync(0xffffffffu, l1, 1);
    l1 += __shfl_xor_sync(0xffffffffu, l1, 2);
    const float inv0 = 1.f / l0, inv1 = 1.f / l1;
    const size_t ybase = (size_t)b * Tn * Cn + (size_t)h * HDn;
    #pragma unroll
    for (int ni = 0; ni < 8; ni++) {
        int d = ni * 8 + c_lane;
        *(__half2*)(y + ybase + (size_t)tr0 * Cn + d) =
            __floats2half2_rn(o[ni][0] * inv0, o[ni][1] * inv0);
        *(__half2*)(y + ybase + (size_t)(tr0 + 8) * Cn + d) =
            __floats2half2_rn(o[ni][2] * inv1, o[ni][3] * inv1);
    }
}

// ---------------- launch ----------------
extern "C" void kernel_launch(void* const* d_in, const int* in_sizes, int n_in,
                              void* d_out, int out_size) {
    const int*   idx   = (const int*)  d_in[0];
    const float* tok   = (const float*)d_in[1];
    const float* pos   = (const float*)d_in[2];
    const float* wq    = (const float*)d_in[3];
    const float* wk    = (const float*)d_in[4];
    const float* wv    = (const float*)d_in[5];
    const float* wo    = (const float*)d_in[6];
    const float* bo    = (const float*)d_in[7];
    const float* ln1g  = (const float*)d_in[8];
    const float* ln1b  = (const float*)d_in[9];
    const float* ln2g  = (const float*)d_in[10];
    const float* ln2b  = (const float*)d_in[11];
    const float* w1    = (const float*)d_in[12];
    const float* b1    = (const float*)d_in[13];
    const float* w2    = (const float*)d_in[14];
    const float* b2    = (const float*)d_in[15];
    const float* lnfg  = (const float*)d_in[16];
    const float* lnfb  = (const float*)d_in[17];
    const float* wlm   = (const float*)d_in[18];
    float* out = (float*)d_out;

    float *x;
    __half *xn, *qkv, *y, *h;
    __half *wqkvH, *woH, *w1H, *w2H, *wlmH;
    cudaGetSymbolAddress((void**)&x,   g_x);
    cudaGetSymbolAddress((void**)&xn,  g_xn);
    cudaGetSymbolAddress((void**)&qkv, g_qkv);
    cudaGetSymbolAddress((void**)&y,   g_y);
    cudaGetSymbolAddress((void**)&h,   g_h);
    cudaGetSymbolAddress((void**)&wqkvH, g_wqkvH);
    cudaGetSymbolAddress((void**)&woH, g_woH);
    cudaGetSymbolAddress((void**)&w1H, g_w1H);
    cudaGetSymbolAddress((void**)&w2H, g_w2H);
    cudaGetSymbolAddress((void**)&wlmH, g_wlmH);

    cudaFuncSetAttribute(gemm_h<false, true, false>,
                         cudaFuncAttributeMaxDynamicSharedMemorySize, GEMM_SMEM);
    cudaFuncSetAttribute(gemm_h<true, true, false>,
                         cudaFuncAttributeMaxDynamicSharedMemorySize, GEMM_SMEM);
    cudaFuncSetAttribute(gemm_h<false, false, false>,
                         cudaFuncAttributeMaxDynamicSharedMemorySize, GEMM_SMEM);
    cudaFuncSetAttribute(gemm_h<false, false, true>,
                         cudaFuncAttributeMaxDynamicSharedMemorySize, GEMM_SMEM);

    round_weights<<<dim3(N_FF / 8 / 256, 7), 256>>>(
        wq, wk, wv, wo, w1, w2, wlm, wqkvH, woH, w1H, w2H, wlmH);
    embed_kernel<<<BT, 256>>>(idx, tok, pos, x);

    const dim3 gQKV(C3 / 128, BT / 128);       // 384
    const dim3 gCCs(Cn / 128, BT / 128, 2);    // 256 (split-K)
    const dim3 gCF(Fn / 128, BT / 128);        // 512
    const dim3 gCV(Vn / 128, BT / 128);        // 4000
    const dim3 gAttn(Tn / 64, Hn, Bn);         // 8 x 16 x 4

    for (int l = 0; l < Ln; l++) {
        const __half* wqkvl = wqkvH + (size_t)l * Cn * C3;
        const __half* woHl = woH + (size_t)l * Cn * Cn;
        const float* bol  = bo + (size_t)l * Cn;
        const __half* w1Hl = w1H + (size_t)l * Cn * Fn;
        const float* b1l  = b1 + (size_t)l * Fn;
        const __half* w2Hl = w2H + (size_t)l * Fn * Cn;
        const float* b2l  = b2 + (size_t)l * Cn;

        ln_kernel<<<BT, 256>>>(x, ln1g + l * Cn, ln1b + l * Cn, xn);
        gemm_h<false, true, false><<<gQKV, 128, GEMM_SMEM>>>(xn, wqkvl, nullptr, nullptr, qkv, C3, Cn);
        attn_mma<<<gAttn, 128>>>(qkv, y);
        gemm_h<false, false, true><<<gCCs, 128, GEMM_SMEM>>>(y, woHl, bol, nullptr, x, Cn, Cn);

        ln_kernel<<<BT, 256>>>(x, ln2g + l * Cn, ln2b + l * Cn, xn);
        gemm_h<true, true, false><<<gCF, 128, GEMM_SMEM>>>(xn, w1Hl, b1l, nullptr, h, Fn, Cn);
        gemm_h<false, false, true><<<gCCs, 128, GEMM_SMEM>>>(h, w2Hl, b2l, nullptr, x, Cn, Fn);
    }

    ln_kernel<<<BT, 256>>>(x, lnfg, lnfb, xn);
    gemm_h<false, false, false><<<gCV, 128, GEMM_SMEM>>>(xn, wlmH, nullptr, nullptr, out, Vn, Cn);
}